// round 1
// baseline (speedup 1.0000x reference)
#include <cuda_runtime.h>
#include <math.h>

#define BB   2
#define SS   4096
#define DD   2048
#define HH   16
#define KVHH 4
#define HDD  128
#define NREP 4

// -------- scratch (device globals; no allocation allowed) --------
__device__ float g_q[(long)BB * SS * HH * HDD];      // [b,s,h*hd]   64 MB
__device__ float g_k[(long)BB * SS * KVHH * HDD];    // [b,s,kvh*hd] 16 MB
__device__ float g_v[(long)BB * SS * KVHH * HDD];    // 16 MB
__device__ float g_attn[(long)BB * SS * HH * HDD];   // 64 MB

// ================= SGEMM: C[M,N] = A[M,K] @ B[K,N], all row-major ==========
// BM=BN=64, BK=16, 256 threads, 4x4 micro-tile. M%64==0, N%64==0, K%16==0.
__global__ __launch_bounds__(256) void sgemm64(
    const float* __restrict__ A, const float* __restrict__ Bm,
    float* __restrict__ C, int M, int N, int K)
{
    __shared__ float As[16][64];   // [k][m]
    __shared__ float Bs[16][64];   // [k][n]

    const int tid = threadIdx.x;
    const int m0 = blockIdx.y * 64;
    const int n0 = blockIdx.x * 64;
    const int ty = tid >> 4;       // 0..15
    const int tx = tid & 15;       // 0..15

    // load mapping
    const int lmA = tid >> 2;            // 0..63 row of A tile
    const int lkA = (tid & 3) * 4;       // k offset 0,4,8,12
    const int lkB = tid >> 4;            // 0..15 k row of B tile
    const int lnB = (tid & 15) * 4;      // n offset

    float acc[4][4] = {};

    const float* Aptr = A + (long)(m0 + lmA) * K + lkA;
    const float* Bptr = Bm + (long)lkB * N + n0 + lnB;

    for (int k0 = 0; k0 < K; k0 += 16) {
        float4 av = *(const float4*)(Aptr + k0);
        As[lkA + 0][lmA] = av.x;
        As[lkA + 1][lmA] = av.y;
        As[lkA + 2][lmA] = av.z;
        As[lkA + 3][lmA] = av.w;
        float4 bv = *(const float4*)(Bptr + (long)k0 * N);
        *(float4*)&Bs[lkB][lnB] = bv;
        __syncthreads();

        #pragma unroll
        for (int k = 0; k < 16; k++) {
            float4 a = *(const float4*)&As[k][ty * 4];
            float4 b = *(const float4*)&Bs[k][tx * 4];
            acc[0][0] += a.x * b.x; acc[0][1] += a.x * b.y; acc[0][2] += a.x * b.z; acc[0][3] += a.x * b.w;
            acc[1][0] += a.y * b.x; acc[1][1] += a.y * b.y; acc[1][2] += a.y * b.z; acc[1][3] += a.y * b.w;
            acc[2][0] += a.z * b.x; acc[2][1] += a.z * b.y; acc[2][2] += a.z * b.z; acc[2][3] += a.z * b.w;
            acc[3][0] += a.w * b.x; acc[3][1] += a.w * b.y; acc[3][2] += a.w * b.z; acc[3][3] += a.w * b.w;
        }
        __syncthreads();
    }

    #pragma unroll
    for (int i = 0; i < 4; i++) {
        float4 v = make_float4(acc[i][0], acc[i][1], acc[i][2], acc[i][3]);
        *(float4*)&C[(long)(m0 + ty * 4 + i) * N + n0 + tx * 4] = v;
    }
}

// ================= RoPE on q and k, in place ================================
// rows = B*S*(H+KVH); each thread handles one (row, d<64) pair.
__global__ void rope_kernel(const float* __restrict__ cosp,
                            const float* __restrict__ sinp)
{
    long idx = (long)blockIdx.x * blockDim.x + threadIdx.x;
    const long total = (long)BB * SS * (HH + KVHH) * 64;
    if (idx >= total) return;
    int d = (int)(idx & 63);
    long row = idx >> 6;
    int head = (int)(row % (HH + KVHH));
    long bs = row / (HH + KVHH);

    float c = cosp[bs * HDD + d];
    float s = sinp[bs * HDD + d];

    float* ptr;
    if (head < HH)
        ptr = g_q + bs * (HH * HDD) + head * HDD;
    else
        ptr = g_k + bs * (KVHH * HDD) + (head - HH) * HDD;

    float x0 = ptr[d];
    float x1 = ptr[d + 64];
    ptr[d]      = x0 * c - x1 * s;
    ptr[d + 64] = x1 * c + x0 * s;
}

// ================= Flash attention (causal, GQA) ============================
// grid = (S/64, H, B), block = 256 threads.
// smem layout (floats): Qt[128][64] | Kt[128][64] | Vs[64][128] | Ss[64][64]
//                       | rowm[64] | rowl[64] | rowc[64]
#define SM_QT 0
#define SM_KT 8192
#define SM_VS 16384
#define SM_SS 24576
#define SM_RM 28672
#define SM_RL 28736
#define SM_RC 28800
#define SM_FLOATS 28864

__global__ __launch_bounds__(256) void flash_attn()
{
    extern __shared__ float sh[];
    float* Qt  = sh + SM_QT;
    float* Kt  = sh + SM_KT;
    float* Vs  = sh + SM_VS;
    float* Ss  = sh + SM_SS;
    float* rowm = sh + SM_RM;
    float* rowl = sh + SM_RL;
    float* rowc = sh + SM_RC;

    const int qt  = blockIdx.x;   // q tile index (64 rows)
    const int h   = blockIdx.y;
    const int b   = blockIdx.z;
    const int kvh = h / NREP;
    const int tid = threadIdx.x;
    const int ty = tid >> 4;      // 0..15
    const int tx = tid & 15;      // 0..15

    // ---- load Q tile transposed: Qt[d][r] ----
    const float* qbase = g_q + ((long)b * SS + (long)qt * 64) * (HH * HDD) + h * HDD;
    for (int i = tid; i < 64 * 32; i += 256) {
        int r  = i >> 5;
        int dv = (i & 31) * 4;
        float4 v = *(const float4*)&qbase[(long)r * (HH * HDD) + dv];
        Qt[(dv + 0) * 64 + r] = v.x;
        Qt[(dv + 1) * 64 + r] = v.y;
        Qt[(dv + 2) * 64 + r] = v.z;
        Qt[(dv + 3) * 64 + r] = v.w;
    }
    if (tid < 64) { rowm[tid] = -1e30f; rowl[tid] = 0.0f; }

    float acc[4][8] = {};
    const float scale = 0.08838834764831845f;   // 1/sqrt(128)

    __syncthreads();

    for (int kt = 0; kt <= qt; kt++) {
        // ---- load K (transposed) and V tiles ----
        const float* kbase = g_k + ((long)b * SS + (long)kt * 64) * (KVHH * HDD) + kvh * HDD;
        const float* vbase = g_v + ((long)b * SS + (long)kt * 64) * (KVHH * HDD) + kvh * HDD;
        for (int i = tid; i < 64 * 32; i += 256) {
            int r  = i >> 5;
            int dv = (i & 31) * 4;
            float4 kv = *(const float4*)&kbase[(long)r * (KVHH * HDD) + dv];
            Kt[(dv + 0) * 64 + r] = kv.x;
            Kt[(dv + 1) * 64 + r] = kv.y;
            Kt[(dv + 2) * 64 + r] = kv.z;
            Kt[(dv + 3) * 64 + r] = kv.w;
            float4 vv = *(const float4*)&vbase[(long)r * (KVHH * HDD) + dv];
            *(float4*)&Vs[r * 128 + dv] = vv;
        }
        __syncthreads();

        // ---- scores: S = Q @ K^T, 4x4 per thread ----
        float s4[4][4] = {};
        #pragma unroll 4
        for (int d = 0; d < 128; d++) {
            float4 a = *(const float4*)&Qt[d * 64 + ty * 4];
            float4 bk = *(const float4*)&Kt[d * 64 + tx * 4];
            s4[0][0] += a.x * bk.x; s4[0][1] += a.x * bk.y; s4[0][2] += a.x * bk.z; s4[0][3] += a.x * bk.w;
            s4[1][0] += a.y * bk.x; s4[1][1] += a.y * bk.y; s4[1][2] += a.y * bk.z; s4[1][3] += a.y * bk.w;
            s4[2][0] += a.z * bk.x; s4[2][1] += a.z * bk.y; s4[2][2] += a.z * bk.z; s4[2][3] += a.z * bk.w;
            s4[3][0] += a.w * bk.x; s4[3][1] += a.w * bk.y; s4[3][2] += a.w * bk.z; s4[3][3] += a.w * bk.w;
        }
        const bool diag = (kt == qt);
        #pragma unroll
        for (int i = 0; i < 4; i++) {
            #pragma unroll
            for (int j = 0; j < 4; j++) {
                float val = s4[i][j] * scale;
                if (diag && (tx * 4 + j) > (ty * 4 + i)) val = -1e30f;
                Ss[(ty * 4 + i) * 64 + tx * 4 + j] = val;
            }
        }
        __syncthreads();

        // ---- online softmax row pass (threads 0..63, one row each) ----
        if (tid < 64) {
            float m_old = rowm[tid];
            float mx = m_old;
            float* srow = &Ss[tid * 64];
            #pragma unroll 8
            for (int c = 0; c < 64; c++) mx = fmaxf(mx, srow[c]);
            float corr = __expf(m_old - mx);
            float sum = 0.0f;
            #pragma unroll 8
            for (int c = 0; c < 64; c++) {
                float e = __expf(srow[c] - mx);
                srow[c] = e;
                sum += e;
            }
            rowl[tid] = rowl[tid] * corr + sum;
            rowm[tid] = mx;
            rowc[tid] = corr;
        }
        __syncthreads();

        // ---- rescale accumulators, then O += P @ V ----
        float cr[4];
        #pragma unroll
        for (int i = 0; i < 4; i++) cr[i] = rowc[ty * 4 + i];
        #pragma unroll
        for (int i = 0; i < 4; i++)
            #pragma unroll
            for (int j = 0; j < 8; j++) acc[i][j] *= cr[i];

        #pragma unroll 4
        for (int kn = 0; kn < 64; kn++) {
            float sv0 = Ss[(ty * 4 + 0) * 64 + kn];
            float sv1 = Ss[(ty * 4 + 1) * 64 + kn];
            float sv2 = Ss[(ty * 4 + 2) * 64 + kn];
            float sv3 = Ss[(ty * 4 + 3) * 64 + kn];
            float4 v0 = *(const float4*)&Vs[kn * 128 + tx * 8];
            float4 v1 = *(const float4*)&Vs[kn * 128 + tx * 8 + 4];
            acc[0][0] += sv0 * v0.x; acc[0][1] += sv0 * v0.y; acc[0][2] += sv0 * v0.z; acc[0][3] += sv0 * v0.w;
            acc[0][4] += sv0 * v1.x; acc[0][5] += sv0 * v1.y; acc[0][6] += sv0 * v1.z; acc[0][7] += sv0 * v1.w;
            acc[1][0] += sv1 * v0.x; acc[1][1] += sv1 * v0.y; acc[1][2] += sv1 * v0.z; acc[1][3] += sv1 * v0.w;
            acc[1][4] += sv1 * v1.x; acc[1][5] += sv1 * v1.y; acc[1][6] += sv1 * v1.z; acc[1][7] += sv1 * v1.w;
            acc[2][0] += sv2 * v0.x; acc[2][1] += sv2 * v0.y; acc[2][2] += sv2 * v0.z; acc[2][3] += sv2 * v0.w;
            acc[2][4] += sv2 * v1.x; acc[2][5] += sv2 * v1.y; acc[2][6] += sv2 * v1.z; acc[2][7] += sv2 * v1.w;
            acc[3][0] += sv3 * v0.x; acc[3][1] += sv3 * v0.y; acc[3][2] += sv3 * v0.z; acc[3][3] += sv3 * v0.w;
            acc[3][4] += sv3 * v1.x; acc[3][5] += sv3 * v1.y; acc[3][6] += sv3 * v1.z; acc[3][7] += sv3 * v1.w;
        }
        __syncthreads();
    }

    // ---- epilogue: divide by l, write [b, s, h*128 + c] ----
    #pragma unroll
    for (int i = 0; i < 4; i++) {
        float linv = 1.0f / rowl[ty * 4 + i];
        long srow = (long)b * SS + (long)qt * 64 + ty * 4 + i;
        float* optr = g_attn + srow * (HH * HDD) + h * HDD + tx * 8;
        float4 o0 = make_float4(acc[i][0] * linv, acc[i][1] * linv,
                                acc[i][2] * linv, acc[i][3] * linv);
        float4 o1 = make_float4(acc[i][4] * linv, acc[i][5] * linv,
                                acc[i][6] * linv, acc[i][7] * linv);
        *(float4*)(optr)     = o0;
        *(float4*)(optr + 4) = o1;
    }
}

// ================= launcher =================================================
extern "C" void kernel_launch(void* const* d_in, const int* in_sizes, int n_in,
                              void* d_out, int out_size)
{
    const float* x    = (const float*)d_in[0];
    const float* cosp = (const float*)d_in[1];
    const float* sinp = (const float*)d_in[2];
    const float* wq   = (const float*)d_in[3];
    const float* wk   = (const float*)d_in[4];
    const float* wv   = (const float*)d_in[5];
    const float* wo   = (const float*)d_in[6];
    float* out = (float*)d_out;

    float *pq, *pk, *pv, *pattn;
    cudaGetSymbolAddress((void**)&pq, g_q);
    cudaGetSymbolAddress((void**)&pk, g_k);
    cudaGetSymbolAddress((void**)&pv, g_v);
    cudaGetSymbolAddress((void**)&pattn, g_attn);

    const int M = BB * SS;  // 8192

    // QKV projections
    sgemm64<<<dim3(DD / 64, M / 64), 256>>>(x, wq, pq, M, DD, DD);
    sgemm64<<<dim3((KVHH * HDD) / 64, M / 64), 256>>>(x, wk, pk, M, KVHH * HDD, DD);
    sgemm64<<<dim3((KVHH * HDD) / 64, M / 64), 256>>>(x, wv, pv, M, KVHH * HDD, DD);

    // RoPE
    {
        long total = (long)BB * SS * (HH + KVHH) * 64;
        int blocks = (int)((total + 255) / 256);
        rope_kernel<<<blocks, 256>>>(cosp, sinp);
    }

    // Flash attention
    {
        size_t smem = (size_t)SM_FLOATS * sizeof(float);  // 115456 B
        cudaFuncSetAttribute(flash_attn, cudaFuncAttributeMaxDynamicSharedMemorySize,
                             (int)smem);
        flash_attn<<<dim3(SS / 64, HH, BB), 256, smem>>>();
    }

    // Output projection
    sgemm64<<<dim3(DD / 64, M / 64), 256>>>(pattn, wo, out, M, DD, DD);
}

// round 2
// speedup vs baseline: 1.4167x; 1.4167x over previous
#include <cuda_runtime.h>
#include <math.h>

#define BB   2
#define SS   4096
#define DD   2048
#define HH   16
#define KVHH 4
#define HDD  128
#define NREP 4

// -------- scratch (device globals; no allocation allowed) --------
__device__ float g_q[(long)BB * SS * HH * HDD];      // [b,s,h*hd]
__device__ float g_k[(long)BB * SS * KVHH * HDD];
__device__ float g_v[(long)BB * SS * KVHH * HDD];
__device__ float g_attn[(long)BB * SS * HH * HDD];

// ===================== TF32 tensor-core GEMM ================================
// C[M,N] = A[M,K] @ B[K,N], row-major. BM=BN=128, BK=16, 256 threads.
// Warps: 2 (m) x 4 (n); warp tile 64x32; mma.sync.m16n8k8 tf32.
// Requires M%128==0, N%128==0, K%16==0.

#define TSTRIDE 132   // padded smem row stride (floats)

__device__ __forceinline__ unsigned f2tf32(float f) {
    unsigned u;
    asm("cvt.rna.tf32.f32 %0, %1;" : "=r"(u) : "f"(f));
    return u;
}

__device__ __forceinline__ void mma_tf32(float c[4], const unsigned a[4],
                                         const unsigned b[2]) {
    asm volatile(
        "mma.sync.aligned.m16n8k8.row.col.f32.tf32.tf32.f32 "
        "{%0,%1,%2,%3}, {%4,%5,%6,%7}, {%8,%9}, {%0,%1,%2,%3};"
        : "+f"(c[0]), "+f"(c[1]), "+f"(c[2]), "+f"(c[3])
        : "r"(a[0]), "r"(a[1]), "r"(a[2]), "r"(a[3]),
          "r"(b[0]), "r"(b[1]));
}

__global__ __launch_bounds__(256) void gemm_tf32(
    const float* __restrict__ A, const float* __restrict__ Bm,
    float* __restrict__ C, int M, int N, int K)
{
    __shared__ float As[2][16 * TSTRIDE];   // [k][m], padded
    __shared__ float Bs[2][16 * TSTRIDE];   // [k][n], padded

    const int tid  = threadIdx.x;
    const int lane = tid & 31;
    const int warp = tid >> 5;
    const int warpM = warp & 1;        // 0..1  (x64 rows)
    const int warpN = warp >> 1;       // 0..3  (x32 cols)
    const int g = lane >> 2;           // 0..7
    const int t = lane & 3;            // 0..3

    const int m0 = blockIdx.y * 128;
    const int n0 = blockIdx.x * 128;

    // global load mapping
    const int arow = tid >> 2;               // slot j=0: rows 0..63 ; j=1: +64 (recompute)
    const int acg  = tid & 3;                // k group (x4)
    const int brow = tid >> 5;               // 0..7 ; j=1: +8
    const int bnc  = (tid & 31) * 4;         // n offset

    float acc[4][4][4] = {};                 // [mi][ni][4]

    // ---- preload stage 0 ----
    {
        #pragma unroll
        for (int j = 0; j < 2; j++) {
            int r = arow + j * 64;
            float4 v = *(const float4*)&A[(long)(m0 + r) * K + acg * 4];
            As[0][(acg * 4 + 0) * TSTRIDE + r] = __uint_as_float(f2tf32(v.x));
            As[0][(acg * 4 + 1) * TSTRIDE + r] = __uint_as_float(f2tf32(v.y));
            As[0][(acg * 4 + 2) * TSTRIDE + r] = __uint_as_float(f2tf32(v.z));
            As[0][(acg * 4 + 3) * TSTRIDE + r] = __uint_as_float(f2tf32(v.w));
        }
        #pragma unroll
        for (int j = 0; j < 2; j++) {
            int kr = brow + j * 8;
            float4 v = *(const float4*)&Bm[(long)kr * N + n0 + bnc];
            float4 o;
            o.x = __uint_as_float(f2tf32(v.x));
            o.y = __uint_as_float(f2tf32(v.y));
            o.z = __uint_as_float(f2tf32(v.z));
            o.w = __uint_as_float(f2tf32(v.w));
            *(float4*)&Bs[0][kr * TSTRIDE + bnc] = o;
        }
    }
    __syncthreads();

    int buf = 0;
    for (int k0 = 0; k0 < K; k0 += 16) {
        // prefetch next stage into registers
        float4 pa[2], pb[2];
        const bool more = (k0 + 16) < K;
        if (more) {
            #pragma unroll
            for (int j = 0; j < 2; j++) {
                int r = arow + j * 64;
                pa[j] = *(const float4*)&A[(long)(m0 + r) * K + k0 + 16 + acg * 4];
            }
            #pragma unroll
            for (int j = 0; j < 2; j++) {
                int kr = brow + j * 8;
                pb[j] = *(const float4*)&Bm[(long)(k0 + 16 + kr) * N + n0 + bnc];
            }
        }

        // compute current stage: 2 k-steps of 8
        const float* as = As[buf];
        const float* bs = Bs[buf];
        #pragma unroll
        for (int ks = 0; ks < 2; ks++) {
            unsigned afr[4][4];
            #pragma unroll
            for (int mi = 0; mi < 4; mi++) {
                int base = (ks * 8 + t) * TSTRIDE + warpM * 64 + mi * 16 + g;
                afr[mi][0] = __float_as_uint(as[base]);
                afr[mi][1] = __float_as_uint(as[base + 8]);
                afr[mi][2] = __float_as_uint(as[base + 4 * TSTRIDE]);
                afr[mi][3] = __float_as_uint(as[base + 4 * TSTRIDE + 8]);
            }
            unsigned bfr[4][2];
            #pragma unroll
            for (int ni = 0; ni < 4; ni++) {
                int base = (ks * 8 + t) * TSTRIDE + warpN * 32 + ni * 8 + g;
                bfr[ni][0] = __float_as_uint(bs[base]);
                bfr[ni][1] = __float_as_uint(bs[base + 4 * TSTRIDE]);
            }
            #pragma unroll
            for (int mi = 0; mi < 4; mi++)
                #pragma unroll
                for (int ni = 0; ni < 4; ni++)
                    mma_tf32(acc[mi][ni], afr[mi], bfr[ni]);
        }

        if (more) {
            int nb = buf ^ 1;
            #pragma unroll
            for (int j = 0; j < 2; j++) {
                int r = arow + j * 64;
                As[nb][(acg * 4 + 0) * TSTRIDE + r] = __uint_as_float(f2tf32(pa[j].x));
                As[nb][(acg * 4 + 1) * TSTRIDE + r] = __uint_as_float(f2tf32(pa[j].y));
                As[nb][(acg * 4 + 2) * TSTRIDE + r] = __uint_as_float(f2tf32(pa[j].z));
                As[nb][(acg * 4 + 3) * TSTRIDE + r] = __uint_as_float(f2tf32(pa[j].w));
            }
            #pragma unroll
            for (int j = 0; j < 2; j++) {
                int kr = brow + j * 8;
                float4 o;
                o.x = __uint_as_float(f2tf32(pb[j].x));
                o.y = __uint_as_float(f2tf32(pb[j].y));
                o.z = __uint_as_float(f2tf32(pb[j].z));
                o.w = __uint_as_float(f2tf32(pb[j].w));
                *(float4*)&Bs[nb][kr * TSTRIDE + bnc] = o;
            }
            __syncthreads();
            buf = nb;
        }
    }

    // ---- epilogue ----
    #pragma unroll
    for (int mi = 0; mi < 4; mi++) {
        int r0 = m0 + warpM * 64 + mi * 16 + g;
        #pragma unroll
        for (int ni = 0; ni < 4; ni++) {
            int c0 = n0 + warpN * 32 + ni * 8 + t * 2;
            float2 lo = make_float2(acc[mi][ni][0], acc[mi][ni][1]);
            float2 hi = make_float2(acc[mi][ni][2], acc[mi][ni][3]);
            *(float2*)&C[(long)r0 * N + c0]       = lo;
            *(float2*)&C[(long)(r0 + 8) * N + c0] = hi;
        }
    }
}

// ================= RoPE on q and k, in place ================================
__global__ void rope_kernel(const float* __restrict__ cosp,
                            const float* __restrict__ sinp)
{
    long idx = (long)blockIdx.x * blockDim.x + threadIdx.x;
    const long total = (long)BB * SS * (HH + KVHH) * 64;
    if (idx >= total) return;
    int d = (int)(idx & 63);
    long row = idx >> 6;
    int head = (int)(row % (HH + KVHH));
    long bs = row / (HH + KVHH);

    float c = cosp[bs * HDD + d];
    float s = sinp[bs * HDD + d];

    float* ptr;
    if (head < HH)
        ptr = g_q + bs * (HH * HDD) + head * HDD;
    else
        ptr = g_k + bs * (KVHH * HDD) + (head - HH) * HDD;

    float x0 = ptr[d];
    float x1 = ptr[d + 64];
    ptr[d]      = x0 * c - x1 * s;
    ptr[d + 64] = x1 * c + x0 * s;
}

// ================= Flash attention (causal, GQA) ============================
#define SM_QT 0
#define SM_KT 8192
#define SM_VS 16384
#define SM_SS 24576
#define SM_RM 28672
#define SM_RL 28736
#define SM_RC 28800
#define SM_FLOATS 28864

__global__ __launch_bounds__(256) void flash_attn()
{
    extern __shared__ float sh[];
    float* Qt  = sh + SM_QT;
    float* Kt  = sh + SM_KT;
    float* Vs  = sh + SM_VS;
    float* Ss  = sh + SM_SS;
    float* rowm = sh + SM_RM;
    float* rowl = sh + SM_RL;
    float* rowc = sh + SM_RC;

    const int qt  = blockIdx.x;
    const int h   = blockIdx.y;
    const int b   = blockIdx.z;
    const int kvh = h / NREP;
    const int tid = threadIdx.x;
    const int ty = tid >> 4;
    const int tx = tid & 15;

    const float* qbase = g_q + ((long)b * SS + (long)qt * 64) * (HH * HDD) + h * HDD;
    for (int i = tid; i < 64 * 32; i += 256) {
        int r  = i >> 5;
        int dv = (i & 31) * 4;
        float4 v = *(const float4*)&qbase[(long)r * (HH * HDD) + dv];
        Qt[(dv + 0) * 64 + r] = v.x;
        Qt[(dv + 1) * 64 + r] = v.y;
        Qt[(dv + 2) * 64 + r] = v.z;
        Qt[(dv + 3) * 64 + r] = v.w;
    }
    if (tid < 64) { rowm[tid] = -1e30f; rowl[tid] = 0.0f; }

    float acc[4][8] = {};
    const float scale = 0.08838834764831845f;

    __syncthreads();

    for (int kt = 0; kt <= qt; kt++) {
        const float* kbase = g_k + ((long)b * SS + (long)kt * 64) * (KVHH * HDD) + kvh * HDD;
        const float* vbase = g_v + ((long)b * SS + (long)kt * 64) * (KVHH * HDD) + kvh * HDD;
        for (int i = tid; i < 64 * 32; i += 256) {
            int r  = i >> 5;
            int dv = (i & 31) * 4;
            float4 kv = *(const float4*)&kbase[(long)r * (KVHH * HDD) + dv];
            Kt[(dv + 0) * 64 + r] = kv.x;
            Kt[(dv + 1) * 64 + r] = kv.y;
            Kt[(dv + 2) * 64 + r] = kv.z;
            Kt[(dv + 3) * 64 + r] = kv.w;
            float4 vv = *(const float4*)&vbase[(long)r * (KVHH * HDD) + dv];
            *(float4*)&Vs[r * 128 + dv] = vv;
        }
        __syncthreads();

        // ---- scores ----
        float s4[4][4] = {};
        #pragma unroll 4
        for (int d = 0; d < 128; d++) {
            float4 a = *(const float4*)&Qt[d * 64 + ty * 4];
            float4 bk = *(const float4*)&Kt[d * 64 + tx * 4];
            s4[0][0] += a.x * bk.x; s4[0][1] += a.x * bk.y; s4[0][2] += a.x * bk.z; s4[0][3] += a.x * bk.w;
            s4[1][0] += a.y * bk.x; s4[1][1] += a.y * bk.y; s4[1][2] += a.y * bk.z; s4[1][3] += a.y * bk.w;
            s4[2][0] += a.z * bk.x; s4[2][1] += a.z * bk.y; s4[2][2] += a.z * bk.z; s4[2][3] += a.z * bk.w;
            s4[3][0] += a.w * bk.x; s4[3][1] += a.w * bk.y; s4[3][2] += a.w * bk.z; s4[3][3] += a.w * bk.w;
        }
        const bool diag = (kt == qt);
        #pragma unroll
        for (int i = 0; i < 4; i++) {
            #pragma unroll
            for (int j = 0; j < 4; j++) {
                float val = s4[i][j] * scale;
                if (diag && (tx * 4 + j) > (ty * 4 + i)) val = -1e30f;
                Ss[(ty * 4 + i) * 64 + tx * 4 + j] = val;
            }
        }
        __syncthreads();

        // ---- parallel online softmax: 4 threads per row ----
        {
            int row = tid >> 2;
            int q4  = tid & 3;
            float* srow = &Ss[row * 64 + q4 * 16];
            float mx = -1e30f;
            #pragma unroll
            for (int c = 0; c < 16; c++) mx = fmaxf(mx, srow[c]);
            mx = fmaxf(mx, __shfl_xor_sync(0xffffffffu, mx, 1));
            mx = fmaxf(mx, __shfl_xor_sync(0xffffffffu, mx, 2));
            float m_old = rowm[row];
            float mnew = fmaxf(m_old, mx);
            float sum = 0.0f;
            #pragma unroll
            for (int c = 0; c < 16; c++) {
                float e = __expf(srow[c] - mnew);
                srow[c] = e;
                sum += e;
            }
            sum += __shfl_xor_sync(0xffffffffu, sum, 1);
            sum += __shfl_xor_sync(0xffffffffu, sum, 2);
            if (q4 == 0) {
                float corr = __expf(m_old - mnew);
                rowl[row] = rowl[row] * corr + sum;
                rowm[row] = mnew;
                rowc[row] = corr;
            }
        }
        __syncthreads();

        // ---- rescale, O += P @ V ----
        float cr[4];
        #pragma unroll
        for (int i = 0; i < 4; i++) cr[i] = rowc[ty * 4 + i];
        #pragma unroll
        for (int i = 0; i < 4; i++)
            #pragma unroll
            for (int j = 0; j < 8; j++) acc[i][j] *= cr[i];

        #pragma unroll 4
        for (int kn = 0; kn < 64; kn++) {
            float sv0 = Ss[(ty * 4 + 0) * 64 + kn];
            float sv1 = Ss[(ty * 4 + 1) * 64 + kn];
            float sv2 = Ss[(ty * 4 + 2) * 64 + kn];
            float sv3 = Ss[(ty * 4 + 3) * 64 + kn];
            float4 v0 = *(const float4*)&Vs[kn * 128 + tx * 8];
            float4 v1 = *(const float4*)&Vs[kn * 128 + tx * 8 + 4];
            acc[0][0] += sv0 * v0.x; acc[0][1] += sv0 * v0.y; acc[0][2] += sv0 * v0.z; acc[0][3] += sv0 * v0.w;
            acc[0][4] += sv0 * v1.x; acc[0][5] += sv0 * v1.y; acc[0][6] += sv0 * v1.z; acc[0][7] += sv0 * v1.w;
            acc[1][0] += sv1 * v0.x; acc[1][1] += sv1 * v0.y; acc[1][2] += sv1 * v0.z; acc[1][3] += sv1 * v0.w;
            acc[1][4] += sv1 * v1.x; acc[1][5] += sv1 * v1.y; acc[1][6] += sv1 * v1.z; acc[1][7] += sv1 * v1.w;
            acc[2][0] += sv2 * v0.x; acc[2][1] += sv2 * v0.y; acc[2][2] += sv2 * v0.z; acc[2][3] += sv2 * v0.w;
            acc[2][4] += sv2 * v1.x; acc[2][5] += sv2 * v1.y; acc[2][6] += sv2 * v1.z; acc[2][7] += sv2 * v1.w;
            acc[3][0] += sv3 * v0.x; acc[3][1] += sv3 * v0.y; acc[3][2] += sv3 * v0.z; acc[3][3] += sv3 * v0.w;
            acc[3][4] += sv3 * v1.x; acc[3][5] += sv3 * v1.y; acc[3][6] += sv3 * v1.z; acc[3][7] += sv3 * v1.w;
        }
        __syncthreads();
    }

    #pragma unroll
    for (int i = 0; i < 4; i++) {
        float linv = 1.0f / rowl[ty * 4 + i];
        long srow = (long)b * SS + (long)qt * 64 + ty * 4 + i;
        float* optr = g_attn + srow * (HH * HDD) + h * HDD + tx * 8;
        float4 o0 = make_float4(acc[i][0] * linv, acc[i][1] * linv,
                                acc[i][2] * linv, acc[i][3] * linv);
        float4 o1 = make_float4(acc[i][4] * linv, acc[i][5] * linv,
                                acc[i][6] * linv, acc[i][7] * linv);
        *(float4*)(optr)     = o0;
        *(float4*)(optr + 4) = o1;
    }
}

// ================= launcher =================================================
extern "C" void kernel_launch(void* const* d_in, const int* in_sizes, int n_in,
                              void* d_out, int out_size)
{
    const float* x    = (const float*)d_in[0];
    const float* cosp = (const float*)d_in[1];
    const float* sinp = (const float*)d_in[2];
    const float* wq   = (const float*)d_in[3];
    const float* wk   = (const float*)d_in[4];
    const float* wv   = (const float*)d_in[5];
    const float* wo   = (const float*)d_in[6];
    float* out = (float*)d_out;

    float *pq, *pk, *pv, *pattn;
    cudaGetSymbolAddress((void**)&pq, g_q);
    cudaGetSymbolAddress((void**)&pk, g_k);
    cudaGetSymbolAddress((void**)&pv, g_v);
    cudaGetSymbolAddress((void**)&pattn, g_attn);

    const int M = BB * SS;  // 8192

    // QKV projections (TF32 tensor cores)
    gemm_tf32<<<dim3(DD / 128, M / 128), 256>>>(x, wq, pq, M, DD, DD);
    gemm_tf32<<<dim3((KVHH * HDD) / 128, M / 128), 256>>>(x, wk, pk, M, KVHH * HDD, DD);
    gemm_tf32<<<dim3((KVHH * HDD) / 128, M / 128), 256>>>(x, wv, pv, M, KVHH * HDD, DD);

    // RoPE
    {
        long total = (long)BB * SS * (HH + KVHH) * 64;
        int blocks = (int)((total + 255) / 256);
        rope_kernel<<<blocks, 256>>>(cosp, sinp);
    }

    // Flash attention
    {
        size_t smem = (size_t)SM_FLOATS * sizeof(float);
        cudaFuncSetAttribute(flash_attn, cudaFuncAttributeMaxDynamicSharedMemorySize,
                             (int)smem);
        flash_attn<<<dim3(SS / 64, HH, BB), 256, smem>>>();
    }

    // Output projection
    gemm_tf32<<<dim3(DD / 128, M / 128), 256>>>(pattn, wo, out, M, DD, DD);
}

// round 3
// speedup vs baseline: 3.9904x; 2.8167x over previous
#include <cuda_runtime.h>
#include <math.h>

#define BB   2
#define SS   4096
#define DD   2048
#define HH   16
#define KVHH 4
#define HDD  128
#define NREP 4

// -------- scratch (device globals; no allocation allowed) --------
__device__ float g_q[(long)BB * SS * HH * HDD];
__device__ float g_k[(long)BB * SS * KVHH * HDD];
__device__ float g_v[(long)BB * SS * KVHH * HDD];
__device__ float g_attn[(long)BB * SS * HH * HDD];

// ===================== shared TF32 helpers ==================================
__device__ __forceinline__ unsigned f2tf32(float f) {
    unsigned u;
    asm("cvt.rna.tf32.f32 %0, %1;" : "=r"(u) : "f"(f));
    return u;
}

__device__ __forceinline__ void mma_tf32(float c[4], const unsigned a[4],
                                         const unsigned b[2]) {
    asm volatile(
        "mma.sync.aligned.m16n8k8.row.col.f32.tf32.tf32.f32 "
        "{%0,%1,%2,%3}, {%4,%5,%6,%7}, {%8,%9}, {%0,%1,%2,%3};"
        : "+f"(c[0]), "+f"(c[1]), "+f"(c[2]), "+f"(c[3])
        : "r"(a[0]), "r"(a[1]), "r"(a[2]), "r"(a[3]),
          "r"(b[0]), "r"(b[1]));
}

// ===================== TF32 tensor-core GEMM ================================
#define TSTRIDE 132

__global__ __launch_bounds__(256) void gemm_tf32(
    const float* __restrict__ A, const float* __restrict__ Bm,
    float* __restrict__ C, int M, int N, int K)
{
    __shared__ float As[2][16 * TSTRIDE];
    __shared__ float Bs[2][16 * TSTRIDE];

    const int tid  = threadIdx.x;
    const int lane = tid & 31;
    const int warp = tid >> 5;
    const int warpM = warp & 1;
    const int warpN = warp >> 1;
    const int g = lane >> 2;
    const int t = lane & 3;

    const int m0 = blockIdx.y * 128;
    const int n0 = blockIdx.x * 128;

    const int arow = tid >> 2;
    const int acg  = tid & 3;
    const int brow = tid >> 5;
    const int bnc  = (tid & 31) * 4;

    float acc[4][4][4] = {};

    {
        #pragma unroll
        for (int j = 0; j < 2; j++) {
            int r = arow + j * 64;
            float4 v = *(const float4*)&A[(long)(m0 + r) * K + acg * 4];
            As[0][(acg * 4 + 0) * TSTRIDE + r] = __uint_as_float(f2tf32(v.x));
            As[0][(acg * 4 + 1) * TSTRIDE + r] = __uint_as_float(f2tf32(v.y));
            As[0][(acg * 4 + 2) * TSTRIDE + r] = __uint_as_float(f2tf32(v.z));
            As[0][(acg * 4 + 3) * TSTRIDE + r] = __uint_as_float(f2tf32(v.w));
        }
        #pragma unroll
        for (int j = 0; j < 2; j++) {
            int kr = brow + j * 8;
            float4 v = *(const float4*)&Bm[(long)kr * N + n0 + bnc];
            float4 o;
            o.x = __uint_as_float(f2tf32(v.x));
            o.y = __uint_as_float(f2tf32(v.y));
            o.z = __uint_as_float(f2tf32(v.z));
            o.w = __uint_as_float(f2tf32(v.w));
            *(float4*)&Bs[0][kr * TSTRIDE + bnc] = o;
        }
    }
    __syncthreads();

    int buf = 0;
    for (int k0 = 0; k0 < K; k0 += 16) {
        float4 pa[2], pb[2];
        const bool more = (k0 + 16) < K;
        if (more) {
            #pragma unroll
            for (int j = 0; j < 2; j++) {
                int r = arow + j * 64;
                pa[j] = *(const float4*)&A[(long)(m0 + r) * K + k0 + 16 + acg * 4];
            }
            #pragma unroll
            for (int j = 0; j < 2; j++) {
                int kr = brow + j * 8;
                pb[j] = *(const float4*)&Bm[(long)(k0 + 16 + kr) * N + n0 + bnc];
            }
        }

        const float* as = As[buf];
        const float* bs = Bs[buf];
        #pragma unroll
        for (int ks = 0; ks < 2; ks++) {
            unsigned afr[4][4];
            #pragma unroll
            for (int mi = 0; mi < 4; mi++) {
                int base = (ks * 8 + t) * TSTRIDE + warpM * 64 + mi * 16 + g;
                afr[mi][0] = __float_as_uint(as[base]);
                afr[mi][1] = __float_as_uint(as[base + 8]);
                afr[mi][2] = __float_as_uint(as[base + 4 * TSTRIDE]);
                afr[mi][3] = __float_as_uint(as[base + 4 * TSTRIDE + 8]);
            }
            unsigned bfr[4][2];
            #pragma unroll
            for (int ni = 0; ni < 4; ni++) {
                int base = (ks * 8 + t) * TSTRIDE + warpN * 32 + ni * 8 + g;
                bfr[ni][0] = __float_as_uint(bs[base]);
                bfr[ni][1] = __float_as_uint(bs[base + 4 * TSTRIDE]);
            }
            #pragma unroll
            for (int mi = 0; mi < 4; mi++)
                #pragma unroll
                for (int ni = 0; ni < 4; ni++)
                    mma_tf32(acc[mi][ni], afr[mi], bfr[ni]);
        }

        if (more) {
            int nb = buf ^ 1;
            #pragma unroll
            for (int j = 0; j < 2; j++) {
                int r = arow + j * 64;
                As[nb][(acg * 4 + 0) * TSTRIDE + r] = __uint_as_float(f2tf32(pa[j].x));
                As[nb][(acg * 4 + 1) * TSTRIDE + r] = __uint_as_float(f2tf32(pa[j].y));
                As[nb][(acg * 4 + 2) * TSTRIDE + r] = __uint_as_float(f2tf32(pa[j].z));
                As[nb][(acg * 4 + 3) * TSTRIDE + r] = __uint_as_float(f2tf32(pa[j].w));
            }
            #pragma unroll
            for (int j = 0; j < 2; j++) {
                int kr = brow + j * 8;
                float4 o;
                o.x = __uint_as_float(f2tf32(pb[j].x));
                o.y = __uint_as_float(f2tf32(pb[j].y));
                o.z = __uint_as_float(f2tf32(pb[j].z));
                o.w = __uint_as_float(f2tf32(pb[j].w));
                *(float4*)&Bs[nb][kr * TSTRIDE + bnc] = o;
            }
            __syncthreads();
            buf = nb;
        }
    }

    #pragma unroll
    for (int mi = 0; mi < 4; mi++) {
        int r0 = m0 + warpM * 64 + mi * 16 + g;
        #pragma unroll
        for (int ni = 0; ni < 4; ni++) {
            int c0 = n0 + warpN * 32 + ni * 8 + t * 2;
            float2 lo = make_float2(acc[mi][ni][0], acc[mi][ni][1]);
            float2 hi = make_float2(acc[mi][ni][2], acc[mi][ni][3]);
            *(float2*)&C[(long)r0 * N + c0]       = lo;
            *(float2*)&C[(long)(r0 + 8) * N + c0] = hi;
        }
    }
}

// ================= RoPE on q and k, in place ================================
__global__ void rope_kernel(const float* __restrict__ cosp,
                            const float* __restrict__ sinp)
{
    long idx = (long)blockIdx.x * blockDim.x + threadIdx.x;
    const long total = (long)BB * SS * (HH + KVHH) * 64;
    if (idx >= total) return;
    int d = (int)(idx & 63);
    long row = idx >> 6;
    int head = (int)(row % (HH + KVHH));
    long bs = row / (HH + KVHH);

    float c = cosp[bs * HDD + d];
    float s = sinp[bs * HDD + d];

    float* ptr;
    if (head < HH)
        ptr = g_q + bs * (HH * HDD) + head * HDD;
    else
        ptr = g_k + bs * (KVHH * HDD) + (head - HH) * HDD;

    float x0 = ptr[d];
    float x1 = ptr[d + 64];
    ptr[d]      = x0 * c - x1 * s;
    ptr[d + 64] = x1 * c + x0 * s;
}

// ================= Flash attention on tensor cores (TF32) ===================
// grid = (S/128, H, B), 256 threads (8 warps x 16 q-rows).
// K/V tiles: 64 rows x 128 d in smem (stride 132). Q frags + O acc in regs.
#define FA_BM 128
#define FA_BN 64
#define FA_STR (HDD + 4)    // 132

__global__ __launch_bounds__(256, 1) void flash_attn_tc()
{
    extern __shared__ float sh[];
    float* Ks = sh;                       // [64][132] tf32
    float* Vs = sh + FA_BN * FA_STR;      // [64][132] tf32

    const int qb  = blockIdx.x;
    const int h   = blockIdx.y;
    const int b   = blockIdx.z;
    const int kvh = h / NREP;
    const int tid  = threadIdx.x;
    const int lane = tid & 31;
    const int warp = tid >> 5;
    const int g = lane >> 2;
    const int t = lane & 3;
    const int woff = warp * 16;
    const unsigned FMASK = 0xffffffffu;
    const float scale = 0.08838834764831845f;   // 1/sqrt(128)

    // ---- stage Q (scaled, tf32) into smem rows 0..127 (spans Ks+Vs) ----
    const float* qbase = g_q + ((long)b * SS + (long)qb * FA_BM) * (HH * HDD) + h * HDD;
    for (int i = tid; i < FA_BM * 32; i += 256) {
        int r = i >> 5, dv = (i & 31) * 4;
        float4 v = *(const float4*)&qbase[(long)r * (HH * HDD) + dv];
        float4 o;
        o.x = __uint_as_float(f2tf32(v.x * scale));
        o.y = __uint_as_float(f2tf32(v.y * scale));
        o.z = __uint_as_float(f2tf32(v.z * scale));
        o.w = __uint_as_float(f2tf32(v.w * scale));
        *(float4*)&sh[r * FA_STR + dv] = o;
    }
    __syncthreads();

    // ---- Q A-fragments into registers: 16 k-steps x 4 regs ----
    unsigned qa[16][4];
    #pragma unroll
    for (int ks = 0; ks < 16; ks++) {
        int base = (woff + g) * FA_STR + ks * 8 + t;
        qa[ks][0] = __float_as_uint(sh[base]);
        qa[ks][1] = __float_as_uint(sh[base + 8 * FA_STR]);
        qa[ks][2] = __float_as_uint(sh[base + 4]);
        qa[ks][3] = __float_as_uint(sh[base + 8 * FA_STR + 4]);
    }

    float o[16][4] = {};
    float m_g = -1e30f, m_g8 = -1e30f, l_g = 0.0f, l_g8 = 0.0f;
    const int rg  = qb * FA_BM + woff + g;
    const int rg8 = rg + 8;
    const int ntiles = 2 * qb + 2;
    const float* kb0 = g_k + ((long)b * SS) * (KVHH * HDD) + kvh * HDD;
    const float* vb0 = g_v + ((long)b * SS) * (KVHH * HDD) + kvh * HDD;
    const int src_lo = (lane & ~3) | (t >> 1);
    const int src_hi = src_lo + 2;

    for (int kt = 0; kt < ntiles; kt++) {
        __syncthreads();   // protect prior reads of Ks/Vs (and Q staging)
        for (int i = tid; i < FA_BN * 32; i += 256) {
            int r = i >> 5, dv = (i & 31) * 4;
            long grow = (long)(kt * FA_BN + r);
            float4 kv = *(const float4*)&kb0[grow * (KVHH * HDD) + dv];
            float4 ko;
            ko.x = __uint_as_float(f2tf32(kv.x));
            ko.y = __uint_as_float(f2tf32(kv.y));
            ko.z = __uint_as_float(f2tf32(kv.z));
            ko.w = __uint_as_float(f2tf32(kv.w));
            *(float4*)&Ks[r * FA_STR + dv] = ko;
            float4 vv = *(const float4*)&vb0[grow * (KVHH * HDD) + dv];
            float4 vo;
            vo.x = __uint_as_float(f2tf32(vv.x));
            vo.y = __uint_as_float(f2tf32(vv.y));
            vo.z = __uint_as_float(f2tf32(vv.z));
            vo.w = __uint_as_float(f2tf32(vv.w));
            *(float4*)&Vs[r * FA_STR + dv] = vo;
        }
        __syncthreads();

        // ---- scores: S[16 x 64] per warp ----
        float s[8][4] = {};
        #pragma unroll
        for (int n = 0; n < 8; n++) {
            #pragma unroll
            for (int ks = 0; ks < 16; ks++) {
                unsigned bfr[2];
                int base = (n * 8 + g) * FA_STR + ks * 8 + t;
                bfr[0] = __float_as_uint(Ks[base]);
                bfr[1] = __float_as_uint(Ks[base + 4]);
                mma_tf32(s[n], qa[ks], bfr);
            }
        }

        // ---- causal mask (only tiles straddling the diagonal) ----
        if (kt * FA_BN + FA_BN - 1 > qb * FA_BM + woff) {
            #pragma unroll
            for (int n = 0; n < 8; n++) {
                int c0 = kt * FA_BN + n * 8 + 2 * t;
                int c1 = c0 + 1;
                if (c0 > rg)  s[n][0] = -1e30f;
                if (c1 > rg)  s[n][1] = -1e30f;
                if (c0 > rg8) s[n][2] = -1e30f;
                if (c1 > rg8) s[n][3] = -1e30f;
            }
        }

        // ---- online softmax in registers ----
        float tm_g = -1e30f, tm_g8 = -1e30f;
        #pragma unroll
        for (int n = 0; n < 8; n++) {
            tm_g  = fmaxf(tm_g,  fmaxf(s[n][0], s[n][1]));
            tm_g8 = fmaxf(tm_g8, fmaxf(s[n][2], s[n][3]));
        }
        tm_g  = fmaxf(tm_g,  __shfl_xor_sync(FMASK, tm_g, 1));
        tm_g  = fmaxf(tm_g,  __shfl_xor_sync(FMASK, tm_g, 2));
        tm_g8 = fmaxf(tm_g8, __shfl_xor_sync(FMASK, tm_g8, 1));
        tm_g8 = fmaxf(tm_g8, __shfl_xor_sync(FMASK, tm_g8, 2));

        float mn_g  = fmaxf(m_g, tm_g);
        float mn_g8 = fmaxf(m_g8, tm_g8);
        float corr_g  = __expf(m_g - mn_g);
        float corr_g8 = __expf(m_g8 - mn_g8);
        m_g = mn_g; m_g8 = mn_g8;

        float sum_g = 0.0f, sum_g8 = 0.0f;
        #pragma unroll
        for (int n = 0; n < 8; n++) {
            s[n][0] = __expf(s[n][0] - m_g);
            s[n][1] = __expf(s[n][1] - m_g);
            s[n][2] = __expf(s[n][2] - m_g8);
            s[n][3] = __expf(s[n][3] - m_g8);
            sum_g  += s[n][0] + s[n][1];
            sum_g8 += s[n][2] + s[n][3];
        }
        sum_g  += __shfl_xor_sync(FMASK, sum_g, 1);
        sum_g  += __shfl_xor_sync(FMASK, sum_g, 2);
        sum_g8 += __shfl_xor_sync(FMASK, sum_g8, 1);
        sum_g8 += __shfl_xor_sync(FMASK, sum_g8, 2);
        l_g  = l_g  * corr_g  + sum_g;
        l_g8 = l_g8 * corr_g8 + sum_g8;

        #pragma unroll
        for (int nn = 0; nn < 16; nn++) {
            o[nn][0] *= corr_g;  o[nn][1] *= corr_g;
            o[nn][2] *= corr_g8; o[nn][3] *= corr_g8;
        }

        // ---- PV: convert P C-frags -> A-frags via shuffles, accumulate ----
        #pragma unroll
        for (int j = 0; j < 8; j++) {
            float x0 = __shfl_sync(FMASK, s[j][0], src_lo);
            float x1 = __shfl_sync(FMASK, s[j][1], src_lo);
            float y0 = __shfl_sync(FMASK, s[j][0], src_hi);
            float y1 = __shfl_sync(FMASK, s[j][1], src_hi);
            float z0 = __shfl_sync(FMASK, s[j][2], src_lo);
            float z1 = __shfl_sync(FMASK, s[j][3], src_lo);
            float w0 = __shfl_sync(FMASK, s[j][2], src_hi);
            float w1 = __shfl_sync(FMASK, s[j][3], src_hi);
            unsigned pa[4];
            pa[0] = f2tf32((t & 1) ? x1 : x0);
            pa[1] = f2tf32((t & 1) ? z1 : z0);
            pa[2] = f2tf32((t & 1) ? y1 : y0);
            pa[3] = f2tf32((t & 1) ? w1 : w0);
            #pragma unroll
            for (int nn = 0; nn < 16; nn++) {
                unsigned bf[2];
                int base = (j * 8 + t) * FA_STR + nn * 8 + g;
                bf[0] = __float_as_uint(Vs[base]);
                bf[1] = __float_as_uint(Vs[base + 4 * FA_STR]);
                mma_tf32(o[nn], pa, bf);
            }
        }
    }

    // ---- epilogue ----
    float il_g = 1.0f / l_g, il_g8 = 1.0f / l_g8;
    long orow = (long)b * SS + qb * FA_BM + woff + g;
    float* obase = g_attn + orow * (HH * HDD) + h * HDD;
    #pragma unroll
    for (int nn = 0; nn < 16; nn++) {
        int col = nn * 8 + 2 * t;
        float2 v0 = make_float2(o[nn][0] * il_g, o[nn][1] * il_g);
        float2 v1 = make_float2(o[nn][2] * il_g8, o[nn][3] * il_g8);
        *(float2*)&obase[col] = v0;
        *(float2*)&obase[(long)8 * (HH * HDD) + col] = v1;
    }
}

// ================= launcher =================================================
extern "C" void kernel_launch(void* const* d_in, const int* in_sizes, int n_in,
                              void* d_out, int out_size)
{
    const float* x    = (const float*)d_in[0];
    const float* cosp = (const float*)d_in[1];
    const float* sinp = (const float*)d_in[2];
    const float* wq   = (const float*)d_in[3];
    const float* wk   = (const float*)d_in[4];
    const float* wv   = (const float*)d_in[5];
    const float* wo   = (const float*)d_in[6];
    float* out = (float*)d_out;

    float *pq, *pk, *pv, *pattn;
    cudaGetSymbolAddress((void**)&pq, g_q);
    cudaGetSymbolAddress((void**)&pk, g_k);
    cudaGetSymbolAddress((void**)&pv, g_v);
    cudaGetSymbolAddress((void**)&pattn, g_attn);

    const int M = BB * SS;  // 8192

    gemm_tf32<<<dim3(DD / 128, M / 128), 256>>>(x, wq, pq, M, DD, DD);
    gemm_tf32<<<dim3((KVHH * HDD) / 128, M / 128), 256>>>(x, wk, pk, M, KVHH * HDD, DD);
    gemm_tf32<<<dim3((KVHH * HDD) / 128, M / 128), 256>>>(x, wv, pv, M, KVHH * HDD, DD);

    {
        long total = (long)BB * SS * (HH + KVHH) * 64;
        int blocks = (int)((total + 255) / 256);
        rope_kernel<<<blocks, 256>>>(cosp, sinp);
    }

    {
        size_t smem = (size_t)(2 * FA_BN * FA_STR) * sizeof(float);  // 67584
        cudaFuncSetAttribute(flash_attn_tc, cudaFuncAttributeMaxDynamicSharedMemorySize,
                             (int)smem);
        flash_attn_tc<<<dim3(SS / FA_BM, HH, BB), 256, smem>>>();
    }

    gemm_tf32<<<dim3(DD / 128, M / 128), 256>>>(pattn, wo, out, M, DD, DD);
}

// round 5
// speedup vs baseline: 4.5247x; 1.1339x over previous
#include <cuda_runtime.h>
#include <cstdint>
#include <math.h>

#define BB   2
#define SS   4096
#define DD   2048
#define HH   16
#define KVHH 4
#define HDD  128
#define NREP 4

// -------- scratch (device globals; no allocation allowed) --------
__device__ float g_q[(long)BB * SS * HH * HDD];
__device__ float g_k[(long)BB * SS * KVHH * HDD];
__device__ float g_v[(long)BB * SS * KVHH * HDD];
__device__ float g_attn[(long)BB * SS * HH * HDD];
__device__ float g_xt[(long)BB * SS * DD];          // tf32-converted x
__device__ float g_wqt[(long)DD * DD];
__device__ float g_wkt[(long)DD * KVHH * HDD];
__device__ float g_wvt[(long)DD * KVHH * HDD];
__device__ float g_wot[(long)DD * DD];

// ===================== helpers ==============================================
__device__ __forceinline__ unsigned f2tf32(float f) {
    unsigned u;
    asm("cvt.rna.tf32.f32 %0, %1;" : "=r"(u) : "f"(f));
    return u;
}

__device__ __forceinline__ uint32_t smem_u32(const void* p) {
    uint32_t a;
    asm("{ .reg .u64 t; cvta.to.shared.u64 t, %1; cvt.u32.u64 %0, t; }"
        : "=r"(a) : "l"(p));
    return a;
}

__device__ __forceinline__ void mma_tf32(float c[4], const unsigned a[4],
                                         const unsigned b[2]) {
    asm volatile(
        "mma.sync.aligned.m16n8k8.row.col.f32.tf32.tf32.f32 "
        "{%0,%1,%2,%3}, {%4,%5,%6,%7}, {%8,%9}, {%0,%1,%2,%3};"
        : "+f"(c[0]), "+f"(c[1]), "+f"(c[2]), "+f"(c[3])
        : "r"(a[0]), "r"(a[1]), "r"(a[2]), "r"(a[3]),
          "r"(b[0]), "r"(b[1]));
}

#define CP_ASYNC16(saddr, gptr) \
    asm volatile("cp.async.cg.shared.global [%0], [%1], 16;" \
                 :: "r"(saddr), "l"(gptr))
#define CP_COMMIT() asm volatile("cp.async.commit_group;" ::: "memory")
#define CP_WAIT2()  asm volatile("cp.async.wait_group 2;" ::: "memory")

// ===================== tf32 pre-conversion ==================================
__global__ void cvt_tf32_kernel(const float* __restrict__ in,
                                float* __restrict__ out, long n4)
{
    long i = (long)blockIdx.x * blockDim.x + threadIdx.x;
    if (i >= n4) return;
    float4 v = ((const float4*)in)[i];
    float4 o;
    o.x = __uint_as_float(f2tf32(v.x));
    o.y = __uint_as_float(f2tf32(v.y));
    o.z = __uint_as_float(f2tf32(v.z));
    o.w = __uint_as_float(f2tf32(v.w));
    ((float4*)out)[i] = o;
}

// ===================== cp.async pipelined TF32 GEMM =========================
// C[M,N] = A[M,K] @ B[K,N], row-major, inputs already tf32-rounded.
// Tile 128x128, BK=16, 256 threads, 4-stage cp.async pipeline.
// As layout [m][k] stride 20; Bs layout [k][n] stride 132 (both conflict-free).
#define ASTR 20
#define BSTR 132
#define STG_A_BYTES (128 * ASTR * 4)            // 10240
#define STG_B_BYTES (16 * BSTR * 4)             // 8448
#define STG_BYTES   (STG_A_BYTES + STG_B_BYTES) // 18688
#define NSTAGE 4
#define GSM_TOTAL (NSTAGE * STG_BYTES)          // 74752

__global__ __launch_bounds__(256, 2) void gemm_cp(
    const float* __restrict__ A, const float* __restrict__ Bm,
    float* __restrict__ C, int M, int N, int K)
{
    extern __shared__ float sh[];
    const uint32_t sbase = smem_u32(sh);

    const int tid  = threadIdx.x;
    const int lane = tid & 31;
    const int warp = tid >> 5;
    const int warpM = warp & 1;
    const int warpN = warp >> 1;
    const int g = lane >> 2;
    const int t = lane & 3;

    const int m0 = blockIdx.y * 128;
    const int n0 = blockIdx.x * 128;

    // cp.async mapping (per thread: 2 A chunks + 2 B chunks of 16B)
    const int ar0 = tid >> 2;            // A chunk row for c=tid (0..63)
    const int akg = tid & 3;             // k group
    const int bkr = tid >> 5;            // B row (0..7), +8 for second
    const int bn4 = (tid & 31) * 4;      // n offset

    float acc[4][4][4] = {};
    const int NS = K >> 4;               // 16-wide stages

    auto issue = [&](int s) {
        const int p = s & (NSTAGE - 1);
        const uint32_t ab = sbase + p * STG_BYTES;
        const uint32_t bb = ab + STG_A_BYTES;
        const int k0 = s << 4;
        // A: rows ar0 and ar0+64
        CP_ASYNC16(ab + (uint32_t)((ar0 * ASTR + akg * 4) * 4),
                   &A[(long)(m0 + ar0) * K + k0 + akg * 4]);
        CP_ASYNC16(ab + (uint32_t)(((ar0 + 64) * ASTR + akg * 4) * 4),
                   &A[(long)(m0 + ar0 + 64) * K + k0 + akg * 4]);
        // B: rows bkr and bkr+8
        CP_ASYNC16(bb + (uint32_t)((bkr * BSTR + bn4) * 4),
                   &Bm[(long)(k0 + bkr) * N + n0 + bn4]);
        CP_ASYNC16(bb + (uint32_t)(((bkr + 8) * BSTR + bn4) * 4),
                   &Bm[(long)(k0 + bkr + 8) * N + n0 + bn4]);
    };

    // prologue: stages 0..2
    issue(0); CP_COMMIT();
    issue(1); CP_COMMIT();
    issue(2); CP_COMMIT();

    for (int s = 0; s < NS; s++) {
        CP_WAIT2();
        __syncthreads();

        if (s + 3 < NS) issue(s + 3);
        CP_COMMIT();                       // empty commit keeps group count uniform

        const int p = s & (NSTAGE - 1);
        const float* as = sh + p * (STG_BYTES / 4);
        const float* bs = as + STG_A_BYTES / 4;

        #pragma unroll
        for (int ks = 0; ks < 2; ks++) {
            unsigned afr[4][4];
            #pragma unroll
            for (int mi = 0; mi < 4; mi++) {
                const float* ap = &as[(warpM * 64 + mi * 16 + g) * ASTR + ks * 8 + t];
                afr[mi][0] = __float_as_uint(ap[0]);
                afr[mi][1] = __float_as_uint(ap[8 * ASTR]);
                afr[mi][2] = __float_as_uint(ap[4]);
                afr[mi][3] = __float_as_uint(ap[8 * ASTR + 4]);
            }
            unsigned bfr[4][2];
            #pragma unroll
            for (int ni = 0; ni < 4; ni++) {
                const float* bp = &bs[(ks * 8 + t) * BSTR + warpN * 32 + ni * 8 + g];
                bfr[ni][0] = __float_as_uint(bp[0]);
                bfr[ni][1] = __float_as_uint(bp[4 * BSTR]);
            }
            #pragma unroll
            for (int mi = 0; mi < 4; mi++)
                #pragma unroll
                for (int ni = 0; ni < 4; ni++)
                    mma_tf32(acc[mi][ni], afr[mi], bfr[ni]);
        }
    }

    #pragma unroll
    for (int mi = 0; mi < 4; mi++) {
        int r0 = m0 + warpM * 64 + mi * 16 + g;
        #pragma unroll
        for (int ni = 0; ni < 4; ni++) {
            int c0 = n0 + warpN * 32 + ni * 8 + t * 2;
            float2 lo = make_float2(acc[mi][ni][0], acc[mi][ni][1]);
            float2 hi = make_float2(acc[mi][ni][2], acc[mi][ni][3]);
            *(float2*)&C[(long)r0 * N + c0]       = lo;
            *(float2*)&C[(long)(r0 + 8) * N + c0] = hi;
        }
    }
}

// ================= RoPE on q and k, in place ================================
__global__ void rope_kernel(const float* __restrict__ cosp,
                            const float* __restrict__ sinp)
{
    long idx = (long)blockIdx.x * blockDim.x + threadIdx.x;
    const long total = (long)BB * SS * (HH + KVHH) * 64;
    if (idx >= total) return;
    int d = (int)(idx & 63);
    long row = idx >> 6;
    int head = (int)(row % (HH + KVHH));
    long bs = row / (HH + KVHH);

    float c = cosp[bs * HDD + d];
    float s = sinp[bs * HDD + d];

    float* ptr;
    if (head < HH)
        ptr = g_q + bs * (HH * HDD) + head * HDD;
    else
        ptr = g_k + bs * (KVHH * HDD) + (head - HH) * HDD;

    float x0 = ptr[d];
    float x1 = ptr[d + 64];
    ptr[d]      = x0 * c - x1 * s;
    ptr[d + 64] = x1 * c + x0 * s;
}

// ================= Flash attention on tensor cores (TF32) ===================
#define FA_BM 128
#define FA_BN 64
#define FA_STR (HDD + 4)    // 132

__global__ __launch_bounds__(256, 1) void flash_attn_tc()
{
    extern __shared__ float sh[];
    float* Ks = sh;
    float* Vs = sh + FA_BN * FA_STR;

    const int qb  = (int)gridDim.x - 1 - (int)blockIdx.x;  // longest first
    const int h   = blockIdx.y;
    const int b   = blockIdx.z;
    const int kvh = h / NREP;
    const int tid  = threadIdx.x;
    const int lane = tid & 31;
    const int warp = tid >> 5;
    const int g = lane >> 2;
    const int t = lane & 3;
    const int woff = warp * 16;
    const unsigned FMASK = 0xffffffffu;
    const float scale = 0.08838834764831845f;

    const float* qbase = g_q + ((long)b * SS + (long)qb * FA_BM) * (HH * HDD) + h * HDD;
    for (int i = tid; i < FA_BM * 32; i += 256) {
        int r = i >> 5, dv = (i & 31) * 4;
        float4 v = *(const float4*)&qbase[(long)r * (HH * HDD) + dv];
        float4 o;
        o.x = __uint_as_float(f2tf32(v.x * scale));
        o.y = __uint_as_float(f2tf32(v.y * scale));
        o.z = __uint_as_float(f2tf32(v.z * scale));
        o.w = __uint_as_float(f2tf32(v.w * scale));
        *(float4*)&sh[r * FA_STR + dv] = o;
    }
    __syncthreads();

    unsigned qa[16][4];
    #pragma unroll
    for (int ks = 0; ks < 16; ks++) {
        int base = (woff + g) * FA_STR + ks * 8 + t;
        qa[ks][0] = __float_as_uint(sh[base]);
        qa[ks][1] = __float_as_uint(sh[base + 8 * FA_STR]);
        qa[ks][2] = __float_as_uint(sh[base + 4]);
        qa[ks][3] = __float_as_uint(sh[base + 8 * FA_STR + 4]);
    }

    float o[16][4] = {};
    float m_g = -1e30f, m_g8 = -1e30f, l_g = 0.0f, l_g8 = 0.0f;
    const int rg  = qb * FA_BM + woff + g;
    const int rg8 = rg + 8;
    const int ntiles = 2 * qb + 2;
    const float* kb0 = g_k + ((long)b * SS) * (KVHH * HDD) + kvh * HDD;
    const float* vb0 = g_v + ((long)b * SS) * (KVHH * HDD) + kvh * HDD;
    const int src_lo = (lane & ~3) | (t >> 1);
    const int src_hi = src_lo + 2;

    for (int kt = 0; kt < ntiles; kt++) {
        __syncthreads();
        for (int i = tid; i < FA_BN * 32; i += 256) {
            int r = i >> 5, dv = (i & 31) * 4;
            long grow = (long)(kt * FA_BN + r);
            float4 kv = *(const float4*)&kb0[grow * (KVHH * HDD) + dv];
            float4 ko;
            ko.x = __uint_as_float(f2tf32(kv.x));
            ko.y = __uint_as_float(f2tf32(kv.y));
            ko.z = __uint_as_float(f2tf32(kv.z));
            ko.w = __uint_as_float(f2tf32(kv.w));
            *(float4*)&Ks[r * FA_STR + dv] = ko;
            float4 vv = *(const float4*)&vb0[grow * (KVHH * HDD) + dv];
            float4 vo;
            vo.x = __uint_as_float(f2tf32(vv.x));
            vo.y = __uint_as_float(f2tf32(vv.y));
            vo.z = __uint_as_float(f2tf32(vv.z));
            vo.w = __uint_as_float(f2tf32(vv.w));
            *(float4*)&Vs[r * FA_STR + dv] = vo;
        }
        __syncthreads();

        float s[8][4] = {};
        #pragma unroll
        for (int n = 0; n < 8; n++) {
            #pragma unroll
            for (int ks = 0; ks < 16; ks++) {
                unsigned bfr[2];
                int base = (n * 8 + g) * FA_STR + ks * 8 + t;
                bfr[0] = __float_as_uint(Ks[base]);
                bfr[1] = __float_as_uint(Ks[base + 4]);
                mma_tf32(s[n], qa[ks], bfr);
            }
        }

        if (kt * FA_BN + FA_BN - 1 > qb * FA_BM + woff) {
            #pragma unroll
            for (int n = 0; n < 8; n++) {
                int c0 = kt * FA_BN + n * 8 + 2 * t;
                int c1 = c0 + 1;
                if (c0 > rg)  s[n][0] = -1e30f;
                if (c1 > rg)  s[n][1] = -1e30f;
                if (c0 > rg8) s[n][2] = -1e30f;
                if (c1 > rg8) s[n][3] = -1e30f;
            }
        }

        float tm_g = -1e30f, tm_g8 = -1e30f;
        #pragma unroll
        for (int n = 0; n < 8; n++) {
            tm_g  = fmaxf(tm_g,  fmaxf(s[n][0], s[n][1]));
            tm_g8 = fmaxf(tm_g8, fmaxf(s[n][2], s[n][3]));
        }
        tm_g  = fmaxf(tm_g,  __shfl_xor_sync(FMASK, tm_g, 1));
        tm_g  = fmaxf(tm_g,  __shfl_xor_sync(FMASK, tm_g, 2));
        tm_g8 = fmaxf(tm_g8, __shfl_xor_sync(FMASK, tm_g8, 1));
        tm_g8 = fmaxf(tm_g8, __shfl_xor_sync(FMASK, tm_g8, 2));

        float mn_g  = fmaxf(m_g, tm_g);
        float mn_g8 = fmaxf(m_g8, tm_g8);
        float corr_g  = __expf(m_g - mn_g);
        float corr_g8 = __expf(m_g8 - mn_g8);
        m_g = mn_g; m_g8 = mn_g8;

        float sum_g = 0.0f, sum_g8 = 0.0f;
        #pragma unroll
        for (int n = 0; n < 8; n++) {
            s[n][0] = __expf(s[n][0] - m_g);
            s[n][1] = __expf(s[n][1] - m_g);
            s[n][2] = __expf(s[n][2] - m_g8);
            s[n][3] = __expf(s[n][3] - m_g8);
            sum_g  += s[n][0] + s[n][1];
            sum_g8 += s[n][2] + s[n][3];
        }
        sum_g  += __shfl_xor_sync(FMASK, sum_g, 1);
        sum_g  += __shfl_xor_sync(FMASK, sum_g, 2);
        sum_g8 += __shfl_xor_sync(FMASK, sum_g8, 1);
        sum_g8 += __shfl_xor_sync(FMASK, sum_g8, 2);
        l_g  = l_g  * corr_g  + sum_g;
        l_g8 = l_g8 * corr_g8 + sum_g8;

        #pragma unroll
        for (int nn = 0; nn < 16; nn++) {
            o[nn][0] *= corr_g;  o[nn][1] *= corr_g;
            o[nn][2] *= corr_g8; o[nn][3] *= corr_g8;
        }

        #pragma unroll
        for (int j = 0; j < 8; j++) {
            float x0 = __shfl_sync(FMASK, s[j][0], src_lo);
            float x1 = __shfl_sync(FMASK, s[j][1], src_lo);
            float y0 = __shfl_sync(FMASK, s[j][0], src_hi);
            float y1 = __shfl_sync(FMASK, s[j][1], src_hi);
            float z0 = __shfl_sync(FMASK, s[j][2], src_lo);
            float z1 = __shfl_sync(FMASK, s[j][3], src_lo);
            float w0 = __shfl_sync(FMASK, s[j][2], src_hi);
            float w1 = __shfl_sync(FMASK, s[j][3], src_hi);
            unsigned pa[4];
            pa[0] = f2tf32((t & 1) ? x1 : x0);
            pa[1] = f2tf32((t & 1) ? z1 : z0);
            pa[2] = f2tf32((t & 1) ? y1 : y0);
            pa[3] = f2tf32((t & 1) ? w1 : w0);
            #pragma unroll
            for (int nn = 0; nn < 16; nn++) {
                unsigned bf[2];
                int base = (j * 8 + t) * FA_STR + nn * 8 + g;
                bf[0] = __float_as_uint(Vs[base]);
                bf[1] = __float_as_uint(Vs[base + 4 * FA_STR]);
                mma_tf32(o[nn], pa, bf);
            }
        }
    }

    // epilogue (tf32-rounded so WO GEMM can consume raw bits)
    float il_g = 1.0f / l_g, il_g8 = 1.0f / l_g8;
    long orow = (long)b * SS + qb * FA_BM + woff + g;
    float* obase = g_attn + orow * (HH * HDD) + h * HDD;
    #pragma unroll
    for (int nn = 0; nn < 16; nn++) {
        int col = nn * 8 + 2 * t;
        float2 v0 = make_float2(__uint_as_float(f2tf32(o[nn][0] * il_g)),
                                __uint_as_float(f2tf32(o[nn][1] * il_g)));
        float2 v1 = make_float2(__uint_as_float(f2tf32(o[nn][2] * il_g8)),
                                __uint_as_float(f2tf32(o[nn][3] * il_g8)));
        *(float2*)&obase[col] = v0;
        *(float2*)&obase[(long)8 * (HH * HDD) + col] = v1;
    }
}

// ================= launcher =================================================
extern "C" void kernel_launch(void* const* d_in, const int* in_sizes, int n_in,
                              void* d_out, int out_size)
{
    const float* x    = (const float*)d_in[0];
    const float* cosp = (const float*)d_in[1];
    const float* sinp = (const float*)d_in[2];
    const float* wq   = (const float*)d_in[3];
    const float* wk   = (const float*)d_in[4];
    const float* wv   = (const float*)d_in[5];
    const float* wo   = (const float*)d_in[6];
    float* out = (float*)d_out;

    float *pq, *pk, *pv, *pattn, *pxt, *pwqt, *pwkt, *pwvt, *pwot;
    cudaGetSymbolAddress((void**)&pq, g_q);
    cudaGetSymbolAddress((void**)&pk, g_k);
    cudaGetSymbolAddress((void**)&pv, g_v);
    cudaGetSymbolAddress((void**)&pattn, g_attn);
    cudaGetSymbolAddress((void**)&pxt, g_xt);
    cudaGetSymbolAddress((void**)&pwqt, g_wqt);
    cudaGetSymbolAddress((void**)&pwkt, g_wkt);
    cudaGetSymbolAddress((void**)&pwvt, g_wvt);
    cudaGetSymbolAddress((void**)&pwot, g_wot);

    const int M = BB * SS;  // 8192

    // pre-convert to tf32
    auto cvt = [&](const float* in, float* outp, long n) {
        long n4 = n / 4;
        cvt_tf32_kernel<<<(unsigned)((n4 + 255) / 256), 256>>>(in, outp, n4);
    };
    cvt(x,  pxt,  (long)M * DD);
    cvt(wq, pwqt, (long)DD * DD);
    cvt(wk, pwkt, (long)DD * KVHH * HDD);
    cvt(wv, pwvt, (long)DD * KVHH * HDD);
    cvt(wo, pwot, (long)DD * DD);

    cudaFuncSetAttribute(gemm_cp, cudaFuncAttributeMaxDynamicSharedMemorySize,
                         GSM_TOTAL);

    // QKV projections
    gemm_cp<<<dim3(DD / 128, M / 128), 256, GSM_TOTAL>>>(pxt, pwqt, pq, M, DD, DD);
    gemm_cp<<<dim3((KVHH * HDD) / 128, M / 128), 256, GSM_TOTAL>>>(pxt, pwkt, pk, M, KVHH * HDD, DD);
    gemm_cp<<<dim3((KVHH * HDD) / 128, M / 128), 256, GSM_TOTAL>>>(pxt, pwvt, pv, M, KVHH * HDD, DD);

    // RoPE
    {
        long total = (long)BB * SS * (HH + KVHH) * 64;
        int blocks = (int)((total + 255) / 256);
        rope_kernel<<<blocks, 256>>>(cosp, sinp);
    }

    // Flash attention
    {
        size_t smem = (size_t)(2 * FA_BN * FA_STR) * sizeof(float);
        cudaFuncSetAttribute(flash_attn_tc, cudaFuncAttributeMaxDynamicSharedMemorySize,
                             (int)smem);
        flash_attn_tc<<<dim3(SS / FA_BM, HH, BB), 256, smem>>>();
    }

    // Output projection
    gemm_cp<<<dim3(DD / 128, M / 128), 256, GSM_TOTAL>>>(pattn, pwot, out, M, DD, DD);
}

// round 6
// speedup vs baseline: 9.0921x; 2.0094x over previous
#include <cuda_runtime.h>
#include <cuda_fp16.h>
#include <cstdint>
#include <math.h>

#define BB   2
#define SS   4096
#define DD   2048
#define HH   16
#define KVHH 4
#define HDD  128
#define NREP 4

// -------- scratch (device globals; no allocation allowed) --------
__device__ __half g_xh[(long)BB * SS * DD];
__device__ __half g_wqh[(long)DD * DD];
__device__ __half g_wkh[(long)DD * KVHH * HDD];
__device__ __half g_wvh[(long)DD * KVHH * HDD];
__device__ __half g_woh[(long)DD * DD];
__device__ __half g_qh[(long)BB * SS * HH * HDD];
__device__ __half g_kh[(long)BB * SS * KVHH * HDD];
__device__ __half g_vh[(long)BB * SS * KVHH * HDD];
__device__ __half g_ah[(long)BB * SS * HH * HDD];

// ===================== helpers ==============================================
__device__ __forceinline__ uint32_t smem_u32(const void* p) {
    uint32_t a;
    asm("{ .reg .u64 t; cvta.to.shared.u64 t, %1; cvt.u32.u64 %0, t; }"
        : "=r"(a) : "l"(p));
    return a;
}

__device__ __forceinline__ void ldsm_x4(uint32_t r[4], uint32_t addr) {
    asm volatile("ldmatrix.sync.aligned.m8n8.x4.shared.b16 {%0,%1,%2,%3}, [%4];"
        : "=r"(r[0]), "=r"(r[1]), "=r"(r[2]), "=r"(r[3]) : "r"(addr));
}
__device__ __forceinline__ void ldsm_x4_t(uint32_t r[4], uint32_t addr) {
    asm volatile("ldmatrix.sync.aligned.m8n8.x4.trans.shared.b16 {%0,%1,%2,%3}, [%4];"
        : "=r"(r[0]), "=r"(r[1]), "=r"(r[2]), "=r"(r[3]) : "r"(addr));
}
__device__ __forceinline__ void mma_f16(float c[4], const uint32_t a[4],
                                        const uint32_t b0, const uint32_t b1) {
    asm volatile(
        "mma.sync.aligned.m16n8k16.row.col.f32.f16.f16.f32 "
        "{%0,%1,%2,%3}, {%4,%5,%6,%7}, {%8,%9}, {%0,%1,%2,%3};"
        : "+f"(c[0]), "+f"(c[1]), "+f"(c[2]), "+f"(c[3])
        : "r"(a[0]), "r"(a[1]), "r"(a[2]), "r"(a[3]), "r"(b0), "r"(b1));
}
__device__ __forceinline__ uint32_t pack_h2(float lo, float hi) {
    __half2 h = __floats2half2_rn(lo, hi);
    return *(uint32_t*)&h;
}

#define CP_ASYNC16(saddr, gptr) \
    asm volatile("cp.async.cg.shared.global [%0], [%1], 16;" \
                 :: "r"(saddr), "l"(gptr))
#define CP_COMMIT() asm volatile("cp.async.commit_group;" ::: "memory")
#define CP_WAIT2()  asm volatile("cp.async.wait_group 2;" ::: "memory")

// ===================== float -> half conversion (with scale) ================
__global__ void cvt_h_kernel(const float* __restrict__ in,
                             __half* __restrict__ out, long n8, float scale)
{
    long i = (long)blockIdx.x * blockDim.x + threadIdx.x;
    if (i >= n8) return;
    const float4* p = (const float4*)in + i * 2;
    float4 v0 = p[0], v1 = p[1];
    __half h[8];
    h[0] = __float2half_rn(v0.x * scale); h[1] = __float2half_rn(v0.y * scale);
    h[2] = __float2half_rn(v0.z * scale); h[3] = __float2half_rn(v0.w * scale);
    h[4] = __float2half_rn(v1.x * scale); h[5] = __float2half_rn(v1.y * scale);
    h[6] = __float2half_rn(v1.z * scale); h[7] = __float2half_rn(v1.w * scale);
    *(uint4*)(out + i * 8) = *(uint4*)h;
}

// ===================== fp16 cp.async pipelined GEMM =========================
// C[M,N] = A[M,K] @ B[K,N] (A,B half; C half or float). Tile 128x128, BK=32.
#define ASTRH 40    // halves
#define BSTRH 136
#define STG_A (128 * ASTRH * 2)   // 10240 B
#define STG_B (32 * BSTRH * 2)    // 8704 B
#define STG   (STG_A + STG_B)     // 18944 B
#define NSTAGE 4
#define GSMEM (NSTAGE * STG)      // 75776 B

template <bool HOUT>
__global__ __launch_bounds__(256, 2) void gemm_hp(
    const __half* __restrict__ A, const __half* __restrict__ Bm,
    void* __restrict__ Cv, int M, int N, int K)
{
    extern __shared__ __half shh[];
    const uint32_t sbase = smem_u32(shh);

    const int tid  = threadIdx.x;
    const int lane = tid & 31;
    const int warp = tid >> 5;
    const int warpM = warp & 1;
    const int warpN = warp >> 1;
    const int g = lane >> 2;
    const int t = lane & 3;
    const int m0 = blockIdx.y * 128;
    const int n0 = blockIdx.x * 128;

    // lane-based ldmatrix address components
    const int lrow8 = ((lane >> 3) & 1) * 8 + (lane & 7);
    const int lcol8 = (lane >> 4) * 8;

    float acc[4][4][4] = {};
    const int NS = K >> 5;

    auto issue = [&](int s) {
        const int p = s & (NSTAGE - 1);
        const uint32_t ab = sbase + p * STG;
        const uint32_t bb = ab + STG_A;
        const int k0 = s << 5;
        // A: 2 chunks per thread
        {
            int c = tid;                   // 0..255
            int r = c >> 2, kg = c & 3;
            CP_ASYNC16(ab + (uint32_t)((r * ASTRH + kg * 8) * 2),
                       &A[(long)(m0 + r) * K + k0 + kg * 8]);
            r += 64;
            CP_ASYNC16(ab + (uint32_t)((r * ASTRH + kg * 8) * 2),
                       &A[(long)(m0 + r) * K + k0 + kg * 8]);
        }
        // B: 2 chunks per thread
        {
            int c = tid;
            int r = c >> 4, nc = c & 15;
            CP_ASYNC16(bb + (uint32_t)((r * BSTRH + nc * 8) * 2),
                       &Bm[(long)(k0 + r) * N + n0 + nc * 8]);
            r += 16;
            CP_ASYNC16(bb + (uint32_t)((r * BSTRH + nc * 8) * 2),
                       &Bm[(long)(k0 + r) * N + n0 + nc * 8]);
        }
    };

    issue(0); CP_COMMIT();
    issue(1); CP_COMMIT();
    issue(2); CP_COMMIT();

    for (int s = 0; s < NS; s++) {
        CP_WAIT2();
        __syncthreads();

        if (s + 3 < NS) issue(s + 3);
        CP_COMMIT();

        const int p = s & (NSTAGE - 1);
        const uint32_t ab = sbase + p * STG;
        const uint32_t bb = ab + STG_A;

        #pragma unroll
        for (int ks = 0; ks < 2; ks++) {
            uint32_t afr[4][4];
            #pragma unroll
            for (int mi = 0; mi < 4; mi++) {
                int row = warpM * 64 + mi * 16 + lrow8;
                int col = ks * 16 + lcol8;
                ldsm_x4(afr[mi], ab + (uint32_t)((row * ASTRH + col) * 2));
            }
            uint32_t bfr[4][2];
            #pragma unroll
            for (int ni2 = 0; ni2 < 2; ni2++) {
                int krow = ks * 16 + lrow8;
                int col  = warpN * 32 + ni2 * 16 + lcol8;
                uint32_t r4[4];
                ldsm_x4_t(r4, bb + (uint32_t)((krow * BSTRH + col) * 2));
                bfr[ni2 * 2][0] = r4[0]; bfr[ni2 * 2][1] = r4[1];
                bfr[ni2 * 2 + 1][0] = r4[2]; bfr[ni2 * 2 + 1][1] = r4[3];
            }
            #pragma unroll
            for (int mi = 0; mi < 4; mi++)
                #pragma unroll
                for (int ni = 0; ni < 4; ni++)
                    mma_f16(acc[mi][ni], afr[mi], bfr[ni][0], bfr[ni][1]);
        }
    }

    #pragma unroll
    for (int mi = 0; mi < 4; mi++) {
        int r0 = m0 + warpM * 64 + mi * 16 + g;
        #pragma unroll
        for (int ni = 0; ni < 4; ni++) {
            int c0 = n0 + warpN * 32 + ni * 8 + t * 2;
            if (HOUT) {
                __half* C = (__half*)Cv;
                *(uint32_t*)&C[(long)r0 * N + c0] =
                    pack_h2(acc[mi][ni][0], acc[mi][ni][1]);
                *(uint32_t*)&C[(long)(r0 + 8) * N + c0] =
                    pack_h2(acc[mi][ni][2], acc[mi][ni][3]);
            } else {
                float* C = (float*)Cv;
                *(float2*)&C[(long)r0 * N + c0] =
                    make_float2(acc[mi][ni][0], acc[mi][ni][1]);
                *(float2*)&C[(long)(r0 + 8) * N + c0] =
                    make_float2(acc[mi][ni][2], acc[mi][ni][3]);
            }
        }
    }
}

// ================= RoPE on half q and k, in place ===========================
__global__ void rope_h_kernel(const float* __restrict__ cosp,
                              const float* __restrict__ sinp)
{
    long idx = (long)blockIdx.x * blockDim.x + threadIdx.x;
    const long total = (long)BB * SS * (HH + KVHH) * 32;
    if (idx >= total) return;
    int d = (int)(idx & 31) * 2;
    long row = idx >> 5;
    int head = (int)(row % (HH + KVHH));
    long bs = row / (HH + KVHH);

    float2 c = *(const float2*)&cosp[bs * HDD + d];
    float2 s = *(const float2*)&sinp[bs * HDD + d];

    __half* ptr;
    if (head < HH)
        ptr = g_qh + bs * (HH * HDD) + head * HDD;
    else
        ptr = g_kh + bs * (KVHH * HDD) + (head - HH) * HDD;

    __half2 x0 = *(__half2*)&ptr[d];
    __half2 x1 = *(__half2*)&ptr[d + 64];
    float x0a = __half2float(x0.x), x0b = __half2float(x0.y);
    float x1a = __half2float(x1.x), x1b = __half2float(x1.y);
    *(__half2*)&ptr[d]      = __floats2half2_rn(x0a * c.x - x1a * s.x,
                                                x0b * c.y - x1b * s.y);
    *(__half2*)&ptr[d + 64] = __floats2half2_rn(x1a * c.x + x0a * s.x,
                                                x1b * c.y + x0b * s.y);
}

// ================= Flash attention (fp16 mma) ===============================
// grid = (S/128, H, B), 256 threads (8 warps x 16 q-rows).
#define FA_BM 128
#define FA_BN 64
#define FA_STRH 136

__global__ __launch_bounds__(256) void flash_attn_hp()
{
    extern __shared__ __half shh[];
    __half* Ks = shh;                         // [64][136]
    __half* Vs = shh + FA_BN * FA_STRH;       // [64][136]
    const uint32_t ks_base = smem_u32(Ks);
    const uint32_t vs_base = smem_u32(Vs);

    const int qb  = (int)gridDim.x - 1 - (int)blockIdx.x;  // longest first
    const int h   = blockIdx.y;
    const int b   = blockIdx.z;
    const int kvh = h / NREP;
    const int tid  = threadIdx.x;
    const int lane = tid & 31;
    const int warp = tid >> 5;
    const int g = lane >> 2;
    const int t = lane & 3;
    const int woff = warp * 16;
    const unsigned FMASK = 0xffffffffu;
    const int lrow8 = ((lane >> 3) & 1) * 8 + (lane & 7);
    const int lcol8 = (lane >> 4) * 8;

    // ---- stage Q (half, pre-scaled via wq) rows 0..127 over Ks+Vs region ----
    const __half* qbase = g_qh + ((long)b * SS + (long)qb * FA_BM) * (HH * HDD) + h * HDD;
    for (int i = tid; i < FA_BM * 16; i += 256) {
        int r = i >> 4, c = (i & 15) * 8;
        uint4 v = *(const uint4*)&qbase[(long)r * (HH * HDD) + c];
        *(uint4*)&shh[r * FA_STRH + c] = v;
    }
    __syncthreads();

    // ---- Q A-fragments: 8 k-steps x 4 regs ----
    uint32_t qa[8][4];
    #pragma unroll
    for (int ks = 0; ks < 8; ks++) {
        int row = woff + lrow8;
        int col = ks * 16 + lcol8;
        ldsm_x4(qa[ks], smem_u32(shh) + (uint32_t)((row * FA_STRH + col) * 2));
    }
    __syncthreads();

    float o[16][4] = {};
    float m_g = -1e30f, m_g8 = -1e30f, l_g = 0.0f, l_g8 = 0.0f;
    const int rg  = qb * FA_BM + woff + g;
    const int rg8 = rg + 8;
    const int ntiles = 2 * qb + 2;
    const __half* kb0 = g_kh + ((long)b * SS) * (KVHH * HDD) + kvh * HDD;
    const __half* vb0 = g_vh + ((long)b * SS) * (KVHH * HDD) + kvh * HDD;

    for (int kt = 0; kt < ntiles; kt++) {
        __syncthreads();
        // ---- stage K and V tiles (64 x 128 halves each) ----
        for (int i = tid; i < FA_BN * 16; i += 256) {
            int r = i >> 4, c = (i & 15) * 8;
            long grow = (long)(kt * FA_BN + r);
            *(uint4*)&Ks[r * FA_STRH + c] = *(const uint4*)&kb0[grow * (KVHH * HDD) + c];
            *(uint4*)&Vs[r * FA_STRH + c] = *(const uint4*)&vb0[grow * (KVHH * HDD) + c];
        }
        __syncthreads();

        // ---- scores: 8 n-blocks x 8 k-steps ----
        float s[8][4] = {};
        #pragma unroll
        for (int n = 0; n < 8; n++) {
            #pragma unroll
            for (int ks = 0; ks < 8; ks++) {
                uint32_t b0 = *(const uint32_t*)&Ks[(n * 8 + g) * FA_STRH + ks * 16 + 2 * t];
                uint32_t b1 = *(const uint32_t*)&Ks[(n * 8 + g) * FA_STRH + ks * 16 + 2 * t + 8];
                mma_f16(s[n], qa[ks], b0, b1);
            }
        }

        // ---- causal mask ----
        if (kt * FA_BN + FA_BN - 1 > qb * FA_BM + woff) {
            #pragma unroll
            for (int n = 0; n < 8; n++) {
                int c0 = kt * FA_BN + n * 8 + 2 * t;
                int c1 = c0 + 1;
                if (c0 > rg)  s[n][0] = -1e30f;
                if (c1 > rg)  s[n][1] = -1e30f;
                if (c0 > rg8) s[n][2] = -1e30f;
                if (c1 > rg8) s[n][3] = -1e30f;
            }
        }

        // ---- online softmax in registers ----
        float tm_g = -1e30f, tm_g8 = -1e30f;
        #pragma unroll
        for (int n = 0; n < 8; n++) {
            tm_g  = fmaxf(tm_g,  fmaxf(s[n][0], s[n][1]));
            tm_g8 = fmaxf(tm_g8, fmaxf(s[n][2], s[n][3]));
        }
        tm_g  = fmaxf(tm_g,  __shfl_xor_sync(FMASK, tm_g, 1));
        tm_g  = fmaxf(tm_g,  __shfl_xor_sync(FMASK, tm_g, 2));
        tm_g8 = fmaxf(tm_g8, __shfl_xor_sync(FMASK, tm_g8, 1));
        tm_g8 = fmaxf(tm_g8, __shfl_xor_sync(FMASK, tm_g8, 2));

        float mn_g  = fmaxf(m_g, tm_g);
        float mn_g8 = fmaxf(m_g8, tm_g8);
        float corr_g  = __expf(m_g - mn_g);
        float corr_g8 = __expf(m_g8 - mn_g8);
        m_g = mn_g; m_g8 = mn_g8;

        float sum_g = 0.0f, sum_g8 = 0.0f;
        #pragma unroll
        for (int n = 0; n < 8; n++) {
            s[n][0] = __expf(s[n][0] - m_g);
            s[n][1] = __expf(s[n][1] - m_g);
            s[n][2] = __expf(s[n][2] - m_g8);
            s[n][3] = __expf(s[n][3] - m_g8);
            sum_g  += s[n][0] + s[n][1];
            sum_g8 += s[n][2] + s[n][3];
        }
        sum_g  += __shfl_xor_sync(FMASK, sum_g, 1);
        sum_g  += __shfl_xor_sync(FMASK, sum_g, 2);
        sum_g8 += __shfl_xor_sync(FMASK, sum_g8, 1);
        sum_g8 += __shfl_xor_sync(FMASK, sum_g8, 2);
        l_g  = l_g  * corr_g  + sum_g;
        l_g8 = l_g8 * corr_g8 + sum_g8;

        #pragma unroll
        for (int nn = 0; nn < 16; nn++) {
            o[nn][0] *= corr_g;  o[nn][1] *= corr_g;
            o[nn][2] *= corr_g8; o[nn][3] *= corr_g8;
        }

        // ---- PV: P C-frags pack directly into fp16 A-frags (no shuffles) ----
        #pragma unroll
        for (int jj = 0; jj < 2; jj++) {
            uint32_t pa0[4], pa1[4];
            {
                int j = 2 * jj;
                pa0[0] = pack_h2(s[2 * j][0],     s[2 * j][1]);
                pa0[1] = pack_h2(s[2 * j][2],     s[2 * j][3]);
                pa0[2] = pack_h2(s[2 * j + 1][0], s[2 * j + 1][1]);
                pa0[3] = pack_h2(s[2 * j + 1][2], s[2 * j + 1][3]);
                j = 2 * jj + 1;
                pa1[0] = pack_h2(s[2 * j][0],     s[2 * j][1]);
                pa1[1] = pack_h2(s[2 * j][2],     s[2 * j][3]);
                pa1[2] = pack_h2(s[2 * j + 1][0], s[2 * j + 1][1]);
                pa1[3] = pack_h2(s[2 * j + 1][2], s[2 * j + 1][3]);
            }
            #pragma unroll
            for (int nn = 0; nn < 16; nn++) {
                int krow = jj * 32 + (lane >> 3) * 8 + (lane & 7);
                uint32_t r4[4];
                ldsm_x4_t(r4, vs_base + (uint32_t)((krow * FA_STRH + nn * 8) * 2));
                mma_f16(o[nn], pa0, r4[0], r4[1]);
                mma_f16(o[nn], pa1, r4[2], r4[3]);
            }
        }
    }

    // ---- epilogue: half output for WO GEMM ----
    float il_g = 1.0f / l_g, il_g8 = 1.0f / l_g8;
    long orow = (long)b * SS + qb * FA_BM + woff + g;
    __half* obase = g_ah + orow * (HH * HDD) + h * HDD;
    #pragma unroll
    for (int nn = 0; nn < 16; nn++) {
        int col = nn * 8 + 2 * t;
        *(uint32_t*)&obase[col] = pack_h2(o[nn][0] * il_g, o[nn][1] * il_g);
        *(uint32_t*)&obase[(long)8 * (HH * HDD) + col] =
            pack_h2(o[nn][2] * il_g8, o[nn][3] * il_g8);
    }
}

// ================= launcher =================================================
extern "C" void kernel_launch(void* const* d_in, const int* in_sizes, int n_in,
                              void* d_out, int out_size)
{
    const float* x    = (const float*)d_in[0];
    const float* cosp = (const float*)d_in[1];
    const float* sinp = (const float*)d_in[2];
    const float* wq   = (const float*)d_in[3];
    const float* wk   = (const float*)d_in[4];
    const float* wv   = (const float*)d_in[5];
    const float* wo   = (const float*)d_in[6];
    float* out = (float*)d_out;

    __half *pxh, *pwqh, *pwkh, *pwvh, *pwoh, *pqh, *pkh, *pvh, *pah;
    cudaGetSymbolAddress((void**)&pxh,  g_xh);
    cudaGetSymbolAddress((void**)&pwqh, g_wqh);
    cudaGetSymbolAddress((void**)&pwkh, g_wkh);
    cudaGetSymbolAddress((void**)&pwvh, g_wvh);
    cudaGetSymbolAddress((void**)&pwoh, g_woh);
    cudaGetSymbolAddress((void**)&pqh,  g_qh);
    cudaGetSymbolAddress((void**)&pkh,  g_kh);
    cudaGetSymbolAddress((void**)&pvh,  g_vh);
    cudaGetSymbolAddress((void**)&pah,  g_ah);

    const int M = BB * SS;  // 8192
    const float scale = 0.08838834764831845f;   // 1/sqrt(128), folded into wq

    auto cvt = [&](const float* in, __half* outp, long n, float s) {
        long n8 = n / 8;
        cvt_h_kernel<<<(unsigned)((n8 + 255) / 256), 256>>>(in, outp, n8, s);
    };
    cvt(x,  pxh,  (long)M * DD, 1.0f);
    cvt(wq, pwqh, (long)DD * DD, scale);
    cvt(wk, pwkh, (long)DD * KVHH * HDD, 1.0f);
    cvt(wv, pwvh, (long)DD * KVHH * HDD, 1.0f);
    cvt(wo, pwoh, (long)DD * DD, 1.0f);

    cudaFuncSetAttribute(gemm_hp<true>, cudaFuncAttributeMaxDynamicSharedMemorySize, GSMEM);
    cudaFuncSetAttribute(gemm_hp<false>, cudaFuncAttributeMaxDynamicSharedMemorySize, GSMEM);

    // QKV projections (q pre-scaled by 1/sqrt(hd))
    gemm_hp<true><<<dim3(DD / 128, M / 128), 256, GSMEM>>>(pxh, pwqh, pqh, M, DD, DD);
    gemm_hp<true><<<dim3((KVHH * HDD) / 128, M / 128), 256, GSMEM>>>(pxh, pwkh, pkh, M, KVHH * HDD, DD);
    gemm_hp<true><<<dim3((KVHH * HDD) / 128, M / 128), 256, GSMEM>>>(pxh, pwvh, pvh, M, KVHH * HDD, DD);

    // RoPE (on halves)
    {
        long total = (long)BB * SS * (HH + KVHH) * 32;
        int blocks = (int)((total + 255) / 256);
        rope_h_kernel<<<blocks, 256>>>(cosp, sinp);
    }

    // Flash attention
    {
        size_t smem = (size_t)(2 * FA_BN * FA_STRH) * sizeof(__half);  // 34816
        cudaFuncSetAttribute(flash_attn_hp, cudaFuncAttributeMaxDynamicSharedMemorySize,
                             (int)smem);
        flash_attn_hp<<<dim3(SS / FA_BM, HH, BB), 256, smem>>>();
    }

    // Output projection (float out)
    gemm_hp<false><<<dim3(DD / 128, M / 128), 256, GSMEM>>>(pah, pwoh, out, M, DD, DD);
}

// round 8
// speedup vs baseline: 9.7323x; 1.0704x over previous
#include <cuda_runtime.h>
#include <cuda_fp16.h>
#include <cstdint>
#include <math.h>

#define BB   2
#define SS   4096
#define DD   2048
#define HH   16
#define KVHH 4
#define HDD  128
#define NREP 4
#define KVSTR (2 * KVHH * HDD)   // 1024 halves: combined k|v row

// -------- scratch (device globals; no allocation allowed) --------
__device__ __half g_xh[(long)BB * SS * DD];
__device__ __half g_wqh[(long)DD * DD];
__device__ __half g_wkv[(long)DD * KVSTR];          // wk cols 0..511, wv cols 512..1023
__device__ __half g_woh[(long)DD * DD];
__device__ __half g_qh[(long)BB * SS * HH * HDD];
__device__ __half g_kvh[(long)BB * SS * KVSTR];     // k|v combined
__device__ __half g_ah[(long)BB * SS * HH * HDD];

// ===================== helpers ==============================================
__device__ __forceinline__ uint32_t smem_u32(const void* p) {
    uint32_t a;
    asm("{ .reg .u64 t; cvta.to.shared.u64 t, %1; cvt.u32.u64 %0, t; }"
        : "=r"(a) : "l"(p));
    return a;
}
__device__ __forceinline__ void ldsm_x4(uint32_t r[4], uint32_t addr) {
    asm volatile("ldmatrix.sync.aligned.m8n8.x4.shared.b16 {%0,%1,%2,%3}, [%4];"
        : "=r"(r[0]), "=r"(r[1]), "=r"(r[2]), "=r"(r[3]) : "r"(addr));
}
__device__ __forceinline__ void ldsm_x4_t(uint32_t r[4], uint32_t addr) {
    asm volatile("ldmatrix.sync.aligned.m8n8.x4.trans.shared.b16 {%0,%1,%2,%3}, [%4];"
        : "=r"(r[0]), "=r"(r[1]), "=r"(r[2]), "=r"(r[3]) : "r"(addr));
}
__device__ __forceinline__ void mma_f16(float c[4], const uint32_t a[4],
                                        const uint32_t b0, const uint32_t b1) {
    asm volatile(
        "mma.sync.aligned.m16n8k16.row.col.f32.f16.f16.f32 "
        "{%0,%1,%2,%3}, {%4,%5,%6,%7}, {%8,%9}, {%0,%1,%2,%3};"
        : "+f"(c[0]), "+f"(c[1]), "+f"(c[2]), "+f"(c[3])
        : "r"(a[0]), "r"(a[1]), "r"(a[2]), "r"(a[3]), "r"(b0), "r"(b1));
}
__device__ __forceinline__ uint32_t pack_h2(float lo, float hi) {
    __half2 h = __floats2half2_rn(lo, hi);
    return *(uint32_t*)&h;
}

#define CP_ASYNC16(saddr, gptr) \
    asm volatile("cp.async.cg.shared.global [%0], [%1], 16;" \
                 :: "r"(saddr), "l"(gptr))
#define CP_COMMIT() asm volatile("cp.async.commit_group;" ::: "memory")
#define CP_WAIT0()  asm volatile("cp.async.wait_group 0;" ::: "memory")
#define CP_WAIT2()  asm volatile("cp.async.wait_group 2;" ::: "memory")

// ===================== float -> half conversion =============================
__global__ void cvt_h_kernel(const float* __restrict__ in,
                             __half* __restrict__ out, long n8, float scale)
{
    long i = (long)blockIdx.x * blockDim.x + threadIdx.x;
    if (i >= n8) return;
    const float4* p = (const float4*)in + i * 2;
    float4 v0 = p[0], v1 = p[1];
    __half h[8];
    h[0] = __float2half_rn(v0.x * scale); h[1] = __float2half_rn(v0.y * scale);
    h[2] = __float2half_rn(v0.z * scale); h[3] = __float2half_rn(v0.w * scale);
    h[4] = __float2half_rn(v1.x * scale); h[5] = __float2half_rn(v1.y * scale);
    h[6] = __float2half_rn(v1.z * scale); h[7] = __float2half_rn(v1.w * scale);
    *(uint4*)(out + i * 8) = *(uint4*)h;
}

// strided variant: in[rows, cols] -> out[rows, ldout] at column offset
__global__ void cvt_h_strided(const float* __restrict__ in,
                              __half* __restrict__ out, long rows, int cols,
                              int ldout, int coloff)
{
    long i = (long)blockIdx.x * blockDim.x + threadIdx.x;
    long n8 = rows * (long)cols / 8;
    if (i >= n8) return;
    int c8pr = cols / 8;
    long r = i / c8pr;
    int c  = (int)(i % c8pr) * 8;
    const float4* p = (const float4*)(in + r * cols + c);
    float4 v0 = p[0], v1 = p[1];
    __half h[8];
    h[0] = __float2half_rn(v0.x); h[1] = __float2half_rn(v0.y);
    h[2] = __float2half_rn(v0.z); h[3] = __float2half_rn(v0.w);
    h[4] = __float2half_rn(v1.x); h[5] = __float2half_rn(v1.y);
    h[6] = __float2half_rn(v1.z); h[7] = __float2half_rn(v1.w);
    *(uint4*)(out + r * ldout + coloff + c) = *(uint4*)h;
}

// ===================== fp16 cp.async GEMM, 128x256 tile =====================
// C[M,N] = A[M,K] @ B[K,N]. 256 threads, 8 warps (2M x 4N), warp tile 64x64.
#define ASTRH 40    // halves
#define BSTRH 264
#define STG_A (128 * ASTRH * 2)   // 10240 B
#define STG_B (32 * BSTRH * 2)    // 16896 B
#define STG   (STG_A + STG_B)     // 27136 B
#define NSTAGE 4
#define GSMEM (NSTAGE * STG)      // 108544 B

template <bool HOUT>
__global__ __launch_bounds__(256, 1) void gemm_hp(
    const __half* __restrict__ A, const __half* __restrict__ Bm,
    void* __restrict__ Cv, int M, int N, int K)
{
    extern __shared__ __half shh[];
    const uint32_t sbase = smem_u32(shh);

    const int tid  = threadIdx.x;
    const int lane = tid & 31;
    const int warp = tid >> 5;
    const int warpM = warp & 1;        // x64 rows
    const int warpN = warp >> 1;       // x64 cols
    const int g = lane >> 2;
    const int t = lane & 3;
    const int m0 = blockIdx.y * 128;
    const int n0 = blockIdx.x * 256;

    const int lrow8 = ((lane >> 3) & 1) * 8 + (lane & 7);
    const int lcol8 = (lane >> 4) * 8;

    float acc[4][8][4] = {};
    const int NS = K >> 5;

    auto issue = [&](int s) {
        const int p = s & (NSTAGE - 1);
        const uint32_t ab = sbase + p * STG;
        const uint32_t bb = ab + STG_A;
        const int k0 = s << 5;
        // A: 2 chunks (rows tid>>2 and +64), 4 k-groups of 8 halves each
        {
            int r = tid >> 2, kg = tid & 3;
            CP_ASYNC16(ab + (uint32_t)((r * ASTRH + kg * 8) * 2),
                       &A[(long)(m0 + r) * K + k0 + kg * 8]);
            r += 64;
            CP_ASYNC16(ab + (uint32_t)((r * ASTRH + kg * 8) * 2),
                       &A[(long)(m0 + r) * K + k0 + kg * 8]);
        }
        // B: 4 chunks; 32 rows x 32 chunks/row = 1024 chunks / 256 threads
        {
            int r0 = tid >> 5, nc = tid & 31;
            #pragma unroll
            for (int j = 0; j < 4; j++) {
                int r = r0 + j * 8;
                CP_ASYNC16(bb + (uint32_t)((r * BSTRH + nc * 8) * 2),
                           &Bm[(long)(k0 + r) * N + n0 + nc * 8]);
            }
        }
    };

    issue(0); CP_COMMIT();
    issue(1); CP_COMMIT();
    issue(2); CP_COMMIT();

    for (int s = 0; s < NS; s++) {
        CP_WAIT2();
        __syncthreads();

        if (s + 3 < NS) issue(s + 3);
        CP_COMMIT();

        const int p = s & (NSTAGE - 1);
        const uint32_t ab = sbase + p * STG;
        const uint32_t bb = ab + STG_A;

        #pragma unroll
        for (int ks = 0; ks < 2; ks++) {
            uint32_t afr[4][4];
            #pragma unroll
            for (int mi = 0; mi < 4; mi++) {
                int row = warpM * 64 + mi * 16 + lrow8;
                int col = ks * 16 + lcol8;
                ldsm_x4(afr[mi], ab + (uint32_t)((row * ASTRH + col) * 2));
            }
            uint32_t bfr[8][2];
            #pragma unroll
            for (int ni2 = 0; ni2 < 4; ni2++) {
                int krow = ks * 16 + lrow8;
                int col  = warpN * 64 + ni2 * 16 + lcol8;
                uint32_t r4[4];
                ldsm_x4_t(r4, bb + (uint32_t)((krow * BSTRH + col) * 2));
                bfr[ni2 * 2][0] = r4[0]; bfr[ni2 * 2][1] = r4[1];
                bfr[ni2 * 2 + 1][0] = r4[2]; bfr[ni2 * 2 + 1][1] = r4[3];
            }
            #pragma unroll
            for (int mi = 0; mi < 4; mi++)
                #pragma unroll
                for (int ni = 0; ni < 8; ni++)
                    mma_f16(acc[mi][ni], afr[mi], bfr[ni][0], bfr[ni][1]);
        }
    }

    #pragma unroll
    for (int mi = 0; mi < 4; mi++) {
        int r0 = m0 + warpM * 64 + mi * 16 + g;
        #pragma unroll
        for (int ni = 0; ni < 8; ni++) {
            int c0 = n0 + warpN * 64 + ni * 8 + t * 2;
            if (HOUT) {
                __half* C = (__half*)Cv;
                *(uint32_t*)&C[(long)r0 * N + c0] =
                    pack_h2(acc[mi][ni][0], acc[mi][ni][1]);
                *(uint32_t*)&C[(long)(r0 + 8) * N + c0] =
                    pack_h2(acc[mi][ni][2], acc[mi][ni][3]);
            } else {
                float* C = (float*)Cv;
                *(float2*)&C[(long)r0 * N + c0] =
                    make_float2(acc[mi][ni][0], acc[mi][ni][1]);
                *(float2*)&C[(long)(r0 + 8) * N + c0] =
                    make_float2(acc[mi][ni][2], acc[mi][ni][3]);
            }
        }
    }
}

// ================= RoPE on half q and k, in place ===========================
__global__ void rope_h_kernel(const float* __restrict__ cosp,
                              const float* __restrict__ sinp)
{
    long idx = (long)blockIdx.x * blockDim.x + threadIdx.x;
    const long total = (long)BB * SS * (HH + KVHH) * 32;
    if (idx >= total) return;
    int d = (int)(idx & 31) * 2;
    long row = idx >> 5;
    int head = (int)(row % (HH + KVHH));
    long bs = row / (HH + KVHH);

    float2 c = *(const float2*)&cosp[bs * HDD + d];
    float2 s = *(const float2*)&sinp[bs * HDD + d];

    __half* ptr;
    if (head < HH)
        ptr = g_qh + bs * (HH * HDD) + head * HDD;
    else
        ptr = g_kvh + bs * KVSTR + (head - HH) * HDD;   // k half of combined buf

    __half2 x0 = *(__half2*)&ptr[d];
    __half2 x1 = *(__half2*)&ptr[d + 64];
    float x0a = __half2float(x0.x), x0b = __half2float(x0.y);
    float x1a = __half2float(x1.x), x1b = __half2float(x1.y);
    *(__half2*)&ptr[d]      = __floats2half2_rn(x0a * c.x - x1a * s.x,
                                                x0b * c.y - x1b * s.y);
    *(__half2*)&ptr[d + 64] = __floats2half2_rn(x1a * c.x + x0a * s.x,
                                                x1b * c.y + x0b * s.y);
}

// ================= Flash attention (fp16 mma, cp.async double buffer) =======
#define FA_BM 128
#define FA_BN 64
#define FA_STRH 136
#define FA_BUF (FA_BN * FA_STRH)   // halves per buffer

__global__ __launch_bounds__(256) void flash_attn_hp()
{
    extern __shared__ __half shh[];
    // layout: [Ks0][Vs0][Ks1][Vs1], each FA_BUF halves
    const uint32_t s0 = smem_u32(shh);

    const int qb  = (int)gridDim.x - 1 - (int)blockIdx.x;  // longest first
    const int h   = blockIdx.y;
    const int b   = blockIdx.z;
    const int kvh = h / NREP;
    const int tid  = threadIdx.x;
    const int lane = tid & 31;
    const int warp = tid >> 5;
    const int g = lane >> 2;
    const int t = lane & 3;
    const int woff = warp * 16;
    const unsigned FMASK = 0xffffffffu;
    const int lrow8 = ((lane >> 3) & 1) * 8 + (lane & 7);
    const int lcol8 = (lane >> 4) * 8;

    // ---- stage Q across smem (128 rows), then keep fragments in regs ----
    const __half* qbase = g_qh + ((long)b * SS + (long)qb * FA_BM) * (HH * HDD) + h * HDD;
    for (int i = tid; i < FA_BM * 16; i += 256) {
        int r = i >> 4, c = (i & 15) * 8;
        *(uint4*)&shh[r * FA_STRH + c] = *(const uint4*)&qbase[(long)r * (HH * HDD) + c];
    }
    __syncthreads();

    uint32_t qa[8][4];
    #pragma unroll
    for (int ks = 0; ks < 8; ks++) {
        int row = woff + lrow8;
        int col = ks * 16 + lcol8;
        ldsm_x4(qa[ks], s0 + (uint32_t)((row * FA_STRH + col) * 2));
    }
    __syncthreads();

    float o[16][4] = {};
    float m_g = -1e30f, m_g8 = -1e30f, l_g = 0.0f, l_g8 = 0.0f;
    const int rg  = qb * FA_BM + woff + g;
    const int rg8 = rg + 8;
    const int ntiles = 2 * qb + 2;
    const __half* kb0 = g_kvh + (long)b * SS * KVSTR + kvh * HDD;
    const __half* vb0 = kb0 + KVHH * HDD;   // v half of combined row

    // per-thread cp.async mapping: 4 chunks K + 4 chunks V
    const int cr = tid >> 4;          // 0..15 base row (+16,+32,+48)
    const int cc = (tid & 15) * 8;    // col halves

    auto issue_tile = [&](int kt, int buf) {
        const uint32_t kb = s0 + (uint32_t)(buf * 2 * FA_BUF * 2);
        const uint32_t vb = kb + (uint32_t)(FA_BUF * 2);
        #pragma unroll
        for (int j = 0; j < 4; j++) {
            int r = cr + j * 16;
            long grow = (long)(kt * FA_BN + r);
            CP_ASYNC16(kb + (uint32_t)((r * FA_STRH + cc) * 2),
                       &kb0[grow * KVSTR + cc]);
            CP_ASYNC16(vb + (uint32_t)((r * FA_STRH + cc) * 2),
                       &vb0[grow * KVSTR + cc]);
        }
    };

    issue_tile(0, 0); CP_COMMIT();

    for (int kt = 0; kt < ntiles; kt++) {
        const int buf = kt & 1;
        CP_WAIT0();
        __syncthreads();   // tile kt visible everywhere

        if (kt + 1 < ntiles) { issue_tile(kt + 1, buf ^ 1); CP_COMMIT(); }

        const uint32_t ksb = s0 + (uint32_t)(buf * 2 * FA_BUF * 2);
        const uint32_t vsb = ksb + (uint32_t)(FA_BUF * 2);
        const __half* Ks = shh + (size_t)buf * 2 * FA_BUF;

        // ---- scores ----
        float s[8][4] = {};
        #pragma unroll
        for (int n = 0; n < 8; n++) {
            #pragma unroll
            for (int ks = 0; ks < 8; ks++) {
                uint32_t b0 = *(const uint32_t*)&Ks[(n * 8 + g) * FA_STRH + ks * 16 + 2 * t];
                uint32_t b1 = *(const uint32_t*)&Ks[(n * 8 + g) * FA_STRH + ks * 16 + 2 * t + 8];
                mma_f16(s[n], qa[ks], b0, b1);
            }
        }

        // ---- causal mask ----
        if (kt * FA_BN + FA_BN - 1 > qb * FA_BM + woff) {
            #pragma unroll
            for (int n = 0; n < 8; n++) {
                int c0 = kt * FA_BN + n * 8 + 2 * t;
                int c1 = c0 + 1;
                if (c0 > rg)  s[n][0] = -1e30f;
                if (c1 > rg)  s[n][1] = -1e30f;
                if (c0 > rg8) s[n][2] = -1e30f;
                if (c1 > rg8) s[n][3] = -1e30f;
            }
        }

        // ---- online softmax ----
        float tm_g = -1e30f, tm_g8 = -1e30f;
        #pragma unroll
        for (int n = 0; n < 8; n++) {
            tm_g  = fmaxf(tm_g,  fmaxf(s[n][0], s[n][1]));
            tm_g8 = fmaxf(tm_g8, fmaxf(s[n][2], s[n][3]));
        }
        tm_g  = fmaxf(tm_g,  __shfl_xor_sync(FMASK, tm_g, 1));
        tm_g  = fmaxf(tm_g,  __shfl_xor_sync(FMASK, tm_g, 2));
        tm_g8 = fmaxf(tm_g8, __shfl_xor_sync(FMASK, tm_g8, 1));
        tm_g8 = fmaxf(tm_g8, __shfl_xor_sync(FMASK, tm_g8, 2));

        float mn_g  = fmaxf(m_g, tm_g);
        float mn_g8 = fmaxf(m_g8, tm_g8);
        float corr_g  = __expf(m_g - mn_g);
        float corr_g8 = __expf(m_g8 - mn_g8);
        m_g = mn_g; m_g8 = mn_g8;

        float sum_g = 0.0f, sum_g8 = 0.0f;
        #pragma unroll
        for (int n = 0; n < 8; n++) {
            s[n][0] = __expf(s[n][0] - m_g);
            s[n][1] = __expf(s[n][1] - m_g);
            s[n][2] = __expf(s[n][2] - m_g8);
            s[n][3] = __expf(s[n][3] - m_g8);
            sum_g  += s[n][0] + s[n][1];
            sum_g8 += s[n][2] + s[n][3];
        }
        sum_g  += __shfl_xor_sync(FMASK, sum_g, 1);
        sum_g  += __shfl_xor_sync(FMASK, sum_g, 2);
        sum_g8 += __shfl_xor_sync(FMASK, sum_g8, 1);
        sum_g8 += __shfl_xor_sync(FMASK, sum_g8, 2);
        l_g  = l_g  * corr_g  + sum_g;
        l_g8 = l_g8 * corr_g8 + sum_g8;

        #pragma unroll
        for (int nn = 0; nn < 16; nn++) {
            o[nn][0] *= corr_g;  o[nn][1] *= corr_g;
            o[nn][2] *= corr_g8; o[nn][3] *= corr_g8;
        }

        // ---- PV ----
        #pragma unroll
        for (int jj = 0; jj < 2; jj++) {
            uint32_t pa0[4], pa1[4];
            {
                int j = 2 * jj;
                pa0[0] = pack_h2(s[2 * j][0],     s[2 * j][1]);
                pa0[1] = pack_h2(s[2 * j][2],     s[2 * j][3]);
                pa0[2] = pack_h2(s[2 * j + 1][0], s[2 * j + 1][1]);
                pa0[3] = pack_h2(s[2 * j + 1][2], s[2 * j + 1][3]);
                j = 2 * jj + 1;
                pa1[0] = pack_h2(s[2 * j][0],     s[2 * j][1]);
                pa1[1] = pack_h2(s[2 * j][2],     s[2 * j][3]);
                pa1[2] = pack_h2(s[2 * j + 1][0], s[2 * j + 1][1]);
                pa1[3] = pack_h2(s[2 * j + 1][2], s[2 * j + 1][3]);
            }
            #pragma unroll
            for (int nn = 0; nn < 16; nn++) {
                int krow = jj * 32 + (lane >> 3) * 8 + (lane & 7);
                uint32_t r4[4];
                ldsm_x4_t(r4, vsb + (uint32_t)((krow * FA_STRH + nn * 8) * 2));
                mma_f16(o[nn], pa0, r4[0], r4[1]);
                mma_f16(o[nn], pa1, r4[2], r4[3]);
            }
        }
        __syncthreads();   // all reads of buf done before it is reissued
    }

    // ---- epilogue ----
    float il_g = 1.0f / l_g, il_g8 = 1.0f / l_g8;
    long orow = (long)b * SS + qb * FA_BM + woff + g;
    __half* obase = g_ah + orow * (HH * HDD) + h * HDD;
    #pragma unroll
    for (int nn = 0; nn < 16; nn++) {
        int col = nn * 8 + 2 * t;
        *(uint32_t*)&obase[col] = pack_h2(o[nn][0] * il_g, o[nn][1] * il_g);
        *(uint32_t*)&obase[(long)8 * (HH * HDD) + col] =
            pack_h2(o[nn][2] * il_g8, o[nn][3] * il_g8);
    }
}

// ================= launcher =================================================
extern "C" void kernel_launch(void* const* d_in, const int* in_sizes, int n_in,
                              void* d_out, int out_size)
{
    const float* x    = (const float*)d_in[0];
    const float* cosp = (const float*)d_in[1];
    const float* sinp = (const float*)d_in[2];
    const float* wq   = (const float*)d_in[3];
    const float* wk   = (const float*)d_in[4];
    const float* wv   = (const float*)d_in[5];
    const float* wo   = (const float*)d_in[6];
    float* out = (float*)d_out;

    __half *pxh, *pwqh, *pwkv, *pwoh, *pqh, *pkvh, *pah;
    cudaGetSymbolAddress((void**)&pxh,  g_xh);
    cudaGetSymbolAddress((void**)&pwqh, g_wqh);
    cudaGetSymbolAddress((void**)&pwkv, g_wkv);
    cudaGetSymbolAddress((void**)&pwoh, g_woh);
    cudaGetSymbolAddress((void**)&pqh,  g_qh);
    cudaGetSymbolAddress((void**)&pkvh, g_kvh);
    cudaGetSymbolAddress((void**)&pah,  g_ah);

    const int M = BB * SS;  // 8192
    const float scale = 0.08838834764831845f;   // 1/sqrt(128), folded into wq

    auto cvt = [&](const float* in, __half* outp, long n, float s) {
        long n8 = n / 8;
        cvt_h_kernel<<<(unsigned)((n8 + 255) / 256), 256>>>(in, outp, n8, s);
    };
    cvt(x,  pxh,  (long)M * DD, 1.0f);
    cvt(wq, pwqh, (long)DD * DD, scale);
    cvt(wo, pwoh, (long)DD * DD, 1.0f);
    {   // wk, wv -> combined [DD, 1024]
        long n8 = (long)DD * (KVHH * HDD) / 8;
        unsigned blks = (unsigned)((n8 + 255) / 256);
        cvt_h_strided<<<blks, 256>>>(wk, pwkv, DD, KVHH * HDD, KVSTR, 0);
        cvt_h_strided<<<blks, 256>>>(wv, pwkv, DD, KVHH * HDD, KVSTR, KVHH * HDD);
    }

    cudaFuncSetAttribute(gemm_hp<true>, cudaFuncAttributeMaxDynamicSharedMemorySize, GSMEM);
    cudaFuncSetAttribute(gemm_hp<false>, cudaFuncAttributeMaxDynamicSharedMemorySize, GSMEM);

    // Q projection (scaled) and fused KV projection
    gemm_hp<true><<<dim3(DD / 256, M / 128), 256, GSMEM>>>(pxh, pwqh, pqh, M, DD, DD);
    gemm_hp<true><<<dim3(KVSTR / 256, M / 128), 256, GSMEM>>>(pxh, pwkv, pkvh, M, KVSTR, DD);

    // RoPE
    {
        long total = (long)BB * SS * (HH + KVHH) * 32;
        int blocks = (int)((total + 255) / 256);
        rope_h_kernel<<<blocks, 256>>>(cosp, sinp);
    }

    // Flash attention (double-buffered)
    {
        size_t smem = (size_t)(4 * FA_BUF) * sizeof(__half);  // 69632
        cudaFuncSetAttribute(flash_attn_hp, cudaFuncAttributeMaxDynamicSharedMemorySize,
                             (int)smem);
        flash_attn_hp<<<dim3(SS / FA_BM, HH, BB), 256, smem>>>();
    }

    // Output projection (float out)
    gemm_hp<false><<<dim3(DD / 256, M / 128), 256, GSMEM>>>(pah, pwoh, out, M, DD, DD);
}